// round 2
// baseline (speedup 1.0000x reference)
#include <cuda_runtime.h>
#include <math.h>

#define BB 2048
#define LL 50
#define FF 64
#define HH 128
#define NOUTS 3
#define G4 512   // 4*H
#define KENC 192 // F + H
#define KDEC 384 // 2H + H

// ---------------- scratch (static device allocations only) ----------------
__device__ float g_h[BB*HH];
__device__ float g_c[BB*HH];
__device__ float g_hde[BB*HH];
__device__ float g_cde[BB*HH];
__device__ float g_xin[BB*FF];
__device__ float g_g[BB*G4];
__device__ float g_enc[BB*LL*HH];
__device__ float g_ctx[BB*HH];
__device__ float g_hproj[BB*HH];
__device__ float g_e2[BB*LL];
__device__ float g_Wenc[KENC*G4];
__device__ float g_benc[G4];
__device__ float g_Wdec[KDEC*G4];
__device__ float g_bdec[G4];

__device__ __forceinline__ float sigf(float v){ return 1.f/(1.f+__expf(-v)); }

// ---------------- init / weight prep ----------------
__global__ void zero_kernel(){
    int idx = blockIdx.x*256 + threadIdx.x;
    if (idx < BB*HH){ g_h[idx]=0.f; g_c[idx]=0.f; g_hde[idx]=0.f; g_cde[idx]=0.f; }
}

__global__ void prep_kernel(const float* __restrict__ eWih, const float* __restrict__ eWhh,
                            const float* __restrict__ ebih, const float* __restrict__ ebhh,
                            const float* __restrict__ dWih, const float* __restrict__ dWhh,
                            const float* __restrict__ dbih, const float* __restrict__ dbhh){
    int idx = blockIdx.x*256 + threadIdx.x;
    if (idx < KENC*G4){
        int k = idx / G4, n = idx % G4;
        g_Wenc[idx] = (k < FF) ? eWih[n*FF + k] : eWhh[n*HH + (k - FF)];
    }
    if (idx < KDEC*G4){
        int k = idx / G4, n = idx % G4;
        g_Wdec[idx] = (k < 256) ? dWih[n*256 + k] : dWhh[n*HH + (k - 256)];
    }
    if (idx < G4){
        g_benc[idx] = ebih[idx] + ebhh[idx];
        g_bdec[idx] = dbih[idx] + dbhh[idx];
    }
}

// ---------------- encoder: input attention (per timestep) ----------------
// e = tanh([x_t, h] @ attn_w[t] + attn_b[t]); xin = softmax(e) * x_t
// BM=32 rows/block, full N=64; 256 threads, 2x4 micro-tile
__global__ void attn_kernel(const float* __restrict__ x, const float* __restrict__ aw,
                            const float* __restrict__ ab, int t){
    __shared__ float As[16][33];
    __shared__ float Bs[16][64];
    __shared__ float Es[32][65];
    __shared__ float rs[32];
    int tid = threadIdx.x;
    int tx = tid & 15, ty = tid >> 4;
    int row0 = blockIdx.x * 32;
    const float* W = aw + t*KENC*FF;
    float acc[2][4] = {};
    for (int k0 = 0; k0 < KENC; k0 += 16){
        for (int i = tid; i < 32*16; i += 256){
            int m = i >> 4, k = i & 15, ka = k0 + k, row = row0 + m;
            As[k][m] = (ka < FF) ? x[(row*LL + t)*FF + ka] : g_h[row*HH + ka - FF];
        }
        for (int i = tid; i < 16*64; i += 256){
            int kk = i >> 6, n = i & 63;
            Bs[kk][n] = W[(k0+kk)*FF + n];
        }
        __syncthreads();
        #pragma unroll
        for (int kk = 0; kk < 16; kk++){
            float a0 = As[kk][ty*2], a1 = As[kk][ty*2+1];
            float4 b = *(const float4*)&Bs[kk][tx*4];
            acc[0][0]+=a0*b.x; acc[0][1]+=a0*b.y; acc[0][2]+=a0*b.z; acc[0][3]+=a0*b.w;
            acc[1][0]+=a1*b.x; acc[1][1]+=a1*b.y; acc[1][2]+=a1*b.z; acc[1][3]+=a1*b.w;
        }
        __syncthreads();
    }
    #pragma unroll
    for (int ii = 0; ii < 2; ii++)
        #pragma unroll
        for (int j = 0; j < 4; j++)
            Es[ty*2+ii][tx*4+j] = tanhf(acc[ii][j] + ab[t*FF + tx*4 + j]);
    __syncthreads();
    if (tid < 32){
        float mx = -1e30f;
        #pragma unroll 4
        for (int j = 0; j < 64; j++) mx = fmaxf(mx, Es[tid][j]);
        float s = 0.f;
        #pragma unroll 4
        for (int j = 0; j < 64; j++){ float e = __expf(Es[tid][j]-mx); Es[tid][j]=e; s+=e; }
        rs[tid] = 1.f/s;
    }
    __syncthreads();
    for (int i = tid; i < 32*64; i += 256){
        int m = i >> 6, j = i & 63, row = row0 + m;
        g_xin[row*FF + j] = Es[m][j]*rs[m]*x[(row*LL + t)*FF + j];
    }
}

// ---------------- encoder LSTM gate GEMM: g = [xin|h] @ Wenc + benc ----------------
// M=2048, N=512, K=192. BM=BN=64, BK=16, 256 threads, 4x4 micro
__global__ void enc_gemm_kernel(){
    __shared__ float As[16][65];
    __shared__ float Bs[16][64];
    int tid = threadIdx.x, tx = tid & 15, ty = tid >> 4;
    int n0 = blockIdx.x*64, row0 = blockIdx.y*64;
    float acc[4][4] = {};
    for (int k0 = 0; k0 < KENC; k0 += 16){
        for (int i = tid; i < 64*16; i += 256){
            int m = i >> 4, k = i & 15, ka = k0 + k, row = row0 + m;
            As[k][m] = (ka < FF) ? g_xin[row*FF + ka] : g_h[row*HH + ka - FF];
        }
        for (int i = tid; i < 16*64; i += 256){
            int kk = i >> 6, n = i & 63;
            Bs[kk][n] = g_Wenc[(k0+kk)*G4 + n0 + n];
        }
        __syncthreads();
        #pragma unroll
        for (int kk = 0; kk < 16; kk++){
            float a[4];
            #pragma unroll
            for (int q = 0; q < 4; q++) a[q] = As[kk][ty*4+q];
            float4 b = *(const float4*)&Bs[kk][tx*4];
            #pragma unroll
            for (int q = 0; q < 4; q++){
                acc[q][0]+=a[q]*b.x; acc[q][1]+=a[q]*b.y; acc[q][2]+=a[q]*b.z; acc[q][3]+=a[q]*b.w;
            }
        }
        __syncthreads();
    }
    #pragma unroll
    for (int q = 0; q < 4; q++){
        int row = row0 + ty*4 + q;
        #pragma unroll
        for (int j = 0; j < 4; j++){
            int n = n0 + tx*4 + j;
            g_g[row*G4 + n] = acc[q][j] + g_benc[n];
        }
    }
}

__global__ void enc_gate_kernel(int t){
    int idx = blockIdx.x*256 + threadIdx.x;  // BB*HH
    int b = idx >> 7, n = idx & 127;
    const float* gr = g_g + b*G4;
    float ig = sigf(gr[n]);
    float fg = sigf(gr[128+n]);
    float gg = tanhf(gr[256+n]);
    float og = sigf(gr[384+n]);
    float c = fg*g_c[idx] + ig*gg;
    g_c[idx] = c;
    float h = og*tanhf(c);
    g_h[idx] = h;
    g_enc[(b*LL + t)*HH + n] = h;
}

// ---------------- decoder: hproj = h_de @ dd_w[i][128:256] + dd_b[i] ----------------
// M=2048, N=128 full, K=128; BM=64, 256 threads, 4x8 micro, grid 32
__global__ void hproj_kernel(const float* __restrict__ ddw, const float* __restrict__ ddb, int step){
    __shared__ float As[16][65];
    __shared__ float Bs[16][128];
    const float* W = ddw + step*256*128 + 128*128;
    int tid = threadIdx.x, tx = tid & 15, ty = tid >> 4;
    int row0 = blockIdx.x*64;
    float acc[4][8] = {};
    for (int k0 = 0; k0 < 128; k0 += 16){
        for (int i = tid; i < 64*16; i += 256){
            int m = i >> 4, k = i & 15, row = row0 + m;
            As[k][m] = g_hde[row*HH + k0 + k];
        }
        for (int i = tid; i < 16*128; i += 256){
            int kk = i >> 7, n = i & 127;
            Bs[kk][n] = W[(k0+kk)*128 + n];
        }
        __syncthreads();
        #pragma unroll
        for (int kk = 0; kk < 16; kk++){
            float a[4];
            #pragma unroll
            for (int q = 0; q < 4; q++) a[q] = As[kk][ty*4+q];
            float4 b0 = *(const float4*)&Bs[kk][tx*8];
            float4 b1 = *(const float4*)&Bs[kk][tx*8+4];
            #pragma unroll
            for (int q = 0; q < 4; q++){
                acc[q][0]+=a[q]*b0.x; acc[q][1]+=a[q]*b0.y; acc[q][2]+=a[q]*b0.z; acc[q][3]+=a[q]*b0.w;
                acc[q][4]+=a[q]*b1.x; acc[q][5]+=a[q]*b1.y; acc[q][6]+=a[q]*b1.z; acc[q][7]+=a[q]*b1.w;
            }
        }
        __syncthreads();
    }
    #pragma unroll
    for (int q = 0; q < 4; q++){
        int row = row0 + ty*4 + q;
        #pragma unroll
        for (int j = 0; j < 8; j++){
            int n = tx*8 + j;
            g_hproj[row*HH + n] = acc[q][j] + ddb[step*128 + n];
        }
    }
}

// ---------------- decoder temporal attention scores (fused epilogue) ----------------
// rows = (b,l), e2[row] = sum_n tanh(enc@dd_w[:128] + hproj[b]) * dl_w + dl_b
__global__ void dattn_kernel(const float* __restrict__ ddw, const float* __restrict__ dlw,
                             const float* __restrict__ dlb, int step){
    __shared__ float As[16][65];
    __shared__ float Bs[16][128];
    __shared__ float sdl[128];
    __shared__ float red[64][17];
    int tid = threadIdx.x, tx = tid & 15, ty = tid >> 4;
    int row0 = blockIdx.x*64;
    if (tid < 128) sdl[tid] = dlw[step*128 + tid];
    const float* W = ddw + step*256*128;
    float acc[4][8] = {};
    for (int k0 = 0; k0 < 128; k0 += 16){
        for (int i = tid; i < 64*16; i += 256){
            int m = i >> 4, k = i & 15, row = row0 + m;
            As[k][m] = g_enc[row*HH + k0 + k];
        }
        for (int i = tid; i < 16*128; i += 256){
            int kk = i >> 7, n = i & 127;
            Bs[kk][n] = W[(k0+kk)*128 + n];
        }
        __syncthreads();
        #pragma unroll
        for (int kk = 0; kk < 16; kk++){
            float a[4];
            #pragma unroll
            for (int q = 0; q < 4; q++) a[q] = As[kk][ty*4+q];
            float4 b0 = *(const float4*)&Bs[kk][tx*8];
            float4 b1 = *(const float4*)&Bs[kk][tx*8+4];
            #pragma unroll
            for (int q = 0; q < 4; q++){
                acc[q][0]+=a[q]*b0.x; acc[q][1]+=a[q]*b0.y; acc[q][2]+=a[q]*b0.z; acc[q][3]+=a[q]*b0.w;
                acc[q][4]+=a[q]*b1.x; acc[q][5]+=a[q]*b1.y; acc[q][6]+=a[q]*b1.z; acc[q][7]+=a[q]*b1.w;
            }
        }
        __syncthreads();
    }
    #pragma unroll
    for (int q = 0; q < 4; q++){
        int row = row0 + ty*4 + q;
        int bb = row / LL;
        float p = 0.f;
        #pragma unroll
        for (int j = 0; j < 8; j++){
            int n = tx*8 + j;
            p += tanhf(acc[q][j] + g_hproj[bb*HH + n]) * sdl[n];
        }
        red[ty*4+q][tx] = p;
    }
    __syncthreads();
    if (tid < 64){
        float s = 0.f;
        #pragma unroll
        for (int xk = 0; xk < 16; xk++) s += red[tid][xk];
        g_e2[row0 + tid] = s + dlb[step];
    }
}

// ---------------- softmax over L + context ----------------
__global__ void softctx_kernel(){
    __shared__ float sal[LL];
    __shared__ float sinv;
    int b = blockIdx.x, tid = threadIdx.x;  // 128 threads
    if (tid < LL) sal[tid] = g_e2[b*LL + tid];
    __syncthreads();
    if (tid == 0){
        float mx = -1e30f;
        for (int l = 0; l < LL; l++) mx = fmaxf(mx, sal[l]);
        float s = 0.f;
        for (int l = 0; l < LL; l++){ float e = __expf(sal[l]-mx); sal[l]=e; s+=e; }
        sinv = 1.f/s;
    }
    __syncthreads();
    float a = 0.f;
    #pragma unroll 5
    for (int l = 0; l < LL; l++) a += sal[l]*g_enc[(b*LL + l)*HH + tid];
    g_ctx[b*HH + tid] = a*sinv;
}

// ---------------- decoder LSTM GEMM: [ctx|h_de|h_de] @ Wdec + bdec ----------------
__global__ void dec_gemm_kernel(){
    __shared__ float As[16][65];
    __shared__ float Bs[16][64];
    int tid = threadIdx.x, tx = tid & 15, ty = tid >> 4;
    int n0 = blockIdx.x*64, row0 = blockIdx.y*64;
    float acc[4][4] = {};
    for (int k0 = 0; k0 < KDEC; k0 += 16){
        for (int i = tid; i < 64*16; i += 256){
            int m = i >> 4, k = i & 15, ka = k0 + k, row = row0 + m;
            float v;
            if (ka < 128)      v = g_ctx[row*HH + ka];
            else if (ka < 256) v = g_hde[row*HH + ka - 128];
            else               v = g_hde[row*HH + ka - 256];
            As[k][m] = v;
        }
        for (int i = tid; i < 16*64; i += 256){
            int kk = i >> 6, n = i & 63;
            Bs[kk][n] = g_Wdec[(k0+kk)*G4 + n0 + n];
        }
        __syncthreads();
        #pragma unroll
        for (int kk = 0; kk < 16; kk++){
            float a[4];
            #pragma unroll
            for (int q = 0; q < 4; q++) a[q] = As[kk][ty*4+q];
            float4 b = *(const float4*)&Bs[kk][tx*4];
            #pragma unroll
            for (int q = 0; q < 4; q++){
                acc[q][0]+=a[q]*b.x; acc[q][1]+=a[q]*b.y; acc[q][2]+=a[q]*b.z; acc[q][3]+=a[q]*b.w;
            }
        }
        __syncthreads();
    }
    #pragma unroll
    for (int q = 0; q < 4; q++){
        int row = row0 + ty*4 + q;
        #pragma unroll
        for (int j = 0; j < 4; j++){
            int n = n0 + tx*4 + j;
            g_g[row*G4 + n] = acc[q][j] + g_bdec[n];
        }
    }
}

__global__ void dec_gate_kernel(){
    int idx = blockIdx.x*256 + threadIdx.x;  // BB*HH
    int b = idx >> 7, n = idx & 127;
    const float* gr = g_g + b*G4;
    float ig = sigf(gr[n]);
    float fg = sigf(gr[128+n]);
    float gg = tanhf(gr[256+n]);
    float og = sigf(gr[384+n]);
    float c = fg*g_cde[idx] + ig*gg;
    g_cde[idx] = c;
    g_hde[idx] = og*tanhf(c);
}

// ---------------- output head: sigmoid(tanh(h@fc_w)+...) ----------------
__global__ void head_kernel(const float* __restrict__ fcw, const float* __restrict__ fcb,
                            const float* __restrict__ ow,  const float* __restrict__ ob,
                            float* __restrict__ out, int step){
    __shared__ float sh[128];
    __shared__ float sp[2];
    int b = blockIdx.x, tid = threadIdx.x;  // 64 threads
    sh[tid]      = g_hde[b*HH + tid];
    sh[tid + 64] = g_hde[b*HH + 64 + tid];
    __syncthreads();
    float s = fcb[step*64 + tid];
    const float* W = fcw + step*HH*64;
    #pragma unroll 8
    for (int k = 0; k < 128; k++) s += sh[k]*W[k*64 + tid];
    float y = tanhf(s)*ow[step*64 + tid];
    #pragma unroll
    for (int off = 16; off; off >>= 1) y += __shfl_down_sync(0xffffffffu, y, off);
    if ((tid & 31) == 0) sp[tid >> 5] = y;
    __syncthreads();
    if (tid == 0){
        float r = sp[0] + sp[1] + ob[step];
        out[b*NOUTS + step] = 1.f/(1.f + __expf(-r));
    }
}

// ---------------- launcher ----------------
extern "C" void kernel_launch(void* const* d_in, const int* in_sizes, int n_in,
                              void* d_out, int out_size){
    const float* x     = (const float*)d_in[0];
    const float* eWih  = (const float*)d_in[1];
    const float* eWhh  = (const float*)d_in[2];
    const float* ebih  = (const float*)d_in[3];
    const float* ebhh  = (const float*)d_in[4];
    const float* attw  = (const float*)d_in[5];
    const float* attb  = (const float*)d_in[6];
    const float* dWih  = (const float*)d_in[7];
    const float* dWhh  = (const float*)d_in[8];
    const float* dbih  = (const float*)d_in[9];
    const float* dbhh  = (const float*)d_in[10];
    const float* ddw   = (const float*)d_in[11];
    const float* ddb   = (const float*)d_in[12];
    const float* dlw   = (const float*)d_in[13];
    const float* dlb   = (const float*)d_in[14];
    const float* fcw   = (const float*)d_in[15];
    const float* fcb   = (const float*)d_in[16];
    const float* ow    = (const float*)d_in[17];
    const float* ob    = (const float*)d_in[18];
    float* out = (float*)d_out;

    zero_kernel<<<(BB*HH + 255)/256, 256>>>();
    prep_kernel<<<(KDEC*G4 + 255)/256, 256>>>(eWih, eWhh, ebih, ebhh, dWih, dWhh, dbih, dbhh);

    for (int t = 0; t < LL; t++){
        attn_kernel<<<BB/32, 256>>>(x, attw, attb, t);
        enc_gemm_kernel<<<dim3(8, 32), 256>>>();
        enc_gate_kernel<<<(BB*HH)/256, 256>>>(t);
    }

    for (int i = 0; i < NOUTS; i++){
        hproj_kernel<<<BB/64, 256>>>(ddw, ddb, i);
        dattn_kernel<<<(BB*LL)/64, 256>>>(ddw, dlw, dlb, i);
        softctx_kernel<<<BB, 128>>>();
        dec_gemm_kernel<<<dim3(8, 32), 256>>>();
        dec_gate_kernel<<<(BB*HH)/256, 256>>>();
        head_kernel<<<BB, 64>>>(fcw, fcb, ow, ob, out, i);
    }
}

// round 3
// speedup vs baseline: 1.4265x; 1.4265x over previous
#include <cuda_runtime.h>
#include <math.h>

#define BB 2048
#define LL 50
#define FF 64
#define HH 128
#define NOUTS 3
#define G4 512   // 4*H
#define KENC 192 // F + H
#define KDEC 384 // 2H + H

// ---------------- scratch (static device allocations only) ----------------
__device__ float g_h[BB*HH];
__device__ float g_c[BB*HH];
__device__ float g_hde[BB*HH];
__device__ float g_cde[BB*HH];
__device__ float g_enc[BB*LL*HH];
__device__ float g_ctx[BB*HH];
__device__ float g_hproj[BB*HH];
__device__ float g_e2[BB*LL];
__device__ float g_Wenc[KENC*G4];
__device__ float g_benc[G4];
__device__ float g_Wdec[KDEC*G4];
__device__ float g_bdec[G4];

__device__ __forceinline__ float sigf(float v){ return 1.f/(1.f+__expf(-v)); }

// ---------------- init / weight prep ----------------
__global__ void zero_kernel(){
    int idx = blockIdx.x*256 + threadIdx.x;
    if (idx < BB*HH){ g_h[idx]=0.f; g_c[idx]=0.f; g_hde[idx]=0.f; g_cde[idx]=0.f; }
}

__global__ void prep_kernel(const float* __restrict__ eWih, const float* __restrict__ eWhh,
                            const float* __restrict__ ebih, const float* __restrict__ ebhh,
                            const float* __restrict__ dWih, const float* __restrict__ dWhh,
                            const float* __restrict__ dbih, const float* __restrict__ dbhh){
    int idx = blockIdx.x*256 + threadIdx.x;
    if (idx < KENC*G4){
        int k = idx / G4, n = idx % G4;
        g_Wenc[idx] = (k < FF) ? eWih[n*FF + k] : eWhh[n*HH + (k - FF)];
    }
    if (idx < KDEC*G4){
        int k = idx / G4, n = idx % G4;
        g_Wdec[idx] = (k < 256) ? dWih[n*256 + k] : dWhh[n*HH + (k - 256)];
    }
    if (idx < G4){
        g_benc[idx] = ebih[idx] + ebhh[idx];
        g_bdec[idx] = dbih[idx] + dbhh[idx];
    }
}

// =======================================================================
// FUSED ENCODER STEP: input-attention + LSTM gate GEMM + gate nonlinearity
// One kernel per timestep. BM=16 rows/block, 128 blocks, 256 threads.
// Shared: sAT[192][17] (A^T: [xin|h]), sE[16][64], sB (16384 floats).
// =======================================================================
__global__ void enc_step_kernel(const float* __restrict__ x,
                                const float* __restrict__ aw,
                                const float* __restrict__ ab, int t){
    extern __shared__ float sm[];
    float* sAT = sm;                 // 192*17 = 3264 floats
    float* sE  = sm + 3264;          // 16*64  = 1024 floats
    float* sB  = sm + 3264 + 1024;   // 16384 floats (phase1: aw_t 192x64; phase2: 32x512 slabs)
    int tid = threadIdx.x;
    int row0 = blockIdx.x * 16;

    // load x_t rows into sAT[0..64) (will become xin in-place)
    for (int i = tid; i < 16*64; i += 256){
        int m = i >> 6, f = i & 63;
        sAT[f*17 + m] = x[((row0+m)*LL + t)*FF + f];
    }
    // load h rows into sAT[64..192)
    for (int i = tid; i < 16*128; i += 256){
        int m = i >> 7, k = i & 127;
        sAT[(64+k)*17 + m] = g_h[(row0+m)*HH + k];
    }
    // stage attention weight aw[t] (192x64) in sB
    const float* W1 = aw + (size_t)t*KENC*FF;
    for (int i = tid; i < KENC*FF; i += 256) sB[i] = W1[i];
    __syncthreads();

    // ---- phase 1: e = tanh([x|h] @ aw_t + ab_t) ----
    {
        int c = tid & 63, m0 = tid >> 6;
        float acc[4] = {};
        #pragma unroll 8
        for (int k = 0; k < KENC; k++){
            float b = sB[k*64 + c];
            #pragma unroll
            for (int q = 0; q < 4; q++)
                acc[q] += sAT[k*17 + m0 + 4*q] * b;
        }
        float bias = ab[t*FF + c];
        #pragma unroll
        for (int q = 0; q < 4; q++)
            sE[(m0+4*q)*64 + c] = tanhf(acc[q] + bias);
    }
    __syncthreads();

    // ---- softmax over 64 features, xin = prob * x (in place into sAT) ----
    {
        int wid = tid >> 5, lane = tid & 31;
        #pragma unroll
        for (int rr = 0; rr < 2; rr++){
            int r = wid*2 + rr;
            float v0 = sE[r*64 + lane], v1 = sE[r*64 + 32 + lane];
            float mx = fmaxf(v0, v1);
            #pragma unroll
            for (int off = 16; off; off >>= 1) mx = fmaxf(mx, __shfl_xor_sync(0xffffffffu, mx, off));
            float e0 = __expf(v0 - mx), e1 = __expf(v1 - mx);
            float s = e0 + e1;
            #pragma unroll
            for (int off = 16; off; off >>= 1) s += __shfl_xor_sync(0xffffffffu, s, off);
            float inv = 1.f/s;
            sAT[lane*17 + r]      *= e0*inv;
            sAT[(lane+32)*17 + r] *= e1*inv;
        }
    }
    __syncthreads();

    // ---- phase 2: g = [xin|h] @ Wenc, fused gates ----
    int tx = tid & 63, ty = tid >> 6;
    float acc[4][8] = {};
    for (int s = 0; s < 6; s++){
        __syncthreads();
        for (int i = tid; i < 32*G4; i += 256)
            sB[i] = g_Wenc[s*32*G4 + i];
        __syncthreads();
        #pragma unroll
        for (int kk = 0; kk < 32; kk++){
            int k = s*32 + kk;
            float a[4];
            #pragma unroll
            for (int q = 0; q < 4; q++) a[q] = sAT[k*17 + ty*4 + q];
            #pragma unroll
            for (int g = 0; g < 4; g++){
                float2 b = *(const float2*)&sB[kk*G4 + g*128 + tx*2];
                #pragma unroll
                for (int q = 0; q < 4; q++){
                    acc[q][g*2]   += a[q]*b.x;
                    acc[q][g*2+1] += a[q]*b.y;
                }
            }
        }
    }
    // gate epilogue
    #pragma unroll
    for (int q = 0; q < 4; q++){
        int row = row0 + ty*4 + q;
        #pragma unroll
        for (int u = 0; u < 2; u++){
            int n = tx*2 + u;
            float ig = sigf (acc[q][0+u] + g_benc[n]);
            float fg = sigf (acc[q][2+u] + g_benc[128+n]);
            float gg = tanhf(acc[q][4+u] + g_benc[256+n]);
            float og = sigf (acc[q][6+u] + g_benc[384+n]);
            float cn = fg*g_c[row*HH + n] + ig*gg;
            g_c[row*HH + n] = cn;
            float h = og*tanhf(cn);
            g_h[row*HH + n] = h;
            g_enc[(row*LL + t)*HH + n] = h;
        }
    }
}

// =======================================================================
// FUSED DECODER LSTM STEP: [ctx|h_de|h_de] @ Wdec + gates
// =======================================================================
__global__ void dec_step_kernel(){
    extern __shared__ float sm[];
    float* sAT = sm;                 // 384*17 = 6528 floats
    float* sB  = sm + 6528;          // 16384 floats
    int tid = threadIdx.x;
    int row0 = blockIdx.x * 16;

    for (int i = tid; i < 16*128; i += 256){
        int m = i >> 7, k = i & 127;
        float ctx = g_ctx[(row0+m)*HH + k];
        float h   = g_hde[(row0+m)*HH + k];
        sAT[k*17 + m]       = ctx;
        sAT[(128+k)*17 + m] = h;
        sAT[(256+k)*17 + m] = h;
    }
    __syncthreads();

    int tx = tid & 63, ty = tid >> 6;
    float acc[4][8] = {};
    for (int s = 0; s < 12; s++){
        __syncthreads();
        for (int i = tid; i < 32*G4; i += 256)
            sB[i] = g_Wdec[s*32*G4 + i];
        __syncthreads();
        #pragma unroll
        for (int kk = 0; kk < 32; kk++){
            int k = s*32 + kk;
            float a[4];
            #pragma unroll
            for (int q = 0; q < 4; q++) a[q] = sAT[k*17 + ty*4 + q];
            #pragma unroll
            for (int g = 0; g < 4; g++){
                float2 b = *(const float2*)&sB[kk*G4 + g*128 + tx*2];
                #pragma unroll
                for (int q = 0; q < 4; q++){
                    acc[q][g*2]   += a[q]*b.x;
                    acc[q][g*2+1] += a[q]*b.y;
                }
            }
        }
    }
    #pragma unroll
    for (int q = 0; q < 4; q++){
        int row = row0 + ty*4 + q;
        #pragma unroll
        for (int u = 0; u < 2; u++){
            int n = tx*2 + u;
            float ig = sigf (acc[q][0+u] + g_bdec[n]);
            float fg = sigf (acc[q][2+u] + g_bdec[128+n]);
            float gg = tanhf(acc[q][4+u] + g_bdec[256+n]);
            float og = sigf (acc[q][6+u] + g_bdec[384+n]);
            float cn = fg*g_cde[row*HH + n] + ig*gg;
            g_cde[row*HH + n] = cn;
            g_hde[row*HH + n] = og*tanhf(cn);
        }
    }
}

// ---------------- decoder: hproj = h_de @ dd_w[i][128:256] + dd_b[i] ----------------
__global__ void hproj_kernel(const float* __restrict__ ddw, const float* __restrict__ ddb, int step){
    __shared__ float As[16][65];
    __shared__ float Bs[16][128];
    const float* W = ddw + step*256*128 + 128*128;
    int tid = threadIdx.x, tx = tid & 15, ty = tid >> 4;
    int row0 = blockIdx.x*64;
    float acc[4][8] = {};
    for (int k0 = 0; k0 < 128; k0 += 16){
        for (int i = tid; i < 64*16; i += 256){
            int m = i >> 4, k = i & 15, row = row0 + m;
            As[k][m] = g_hde[row*HH + k0 + k];
        }
        for (int i = tid; i < 16*128; i += 256){
            int kk = i >> 7, n = i & 127;
            Bs[kk][n] = W[(k0+kk)*128 + n];
        }
        __syncthreads();
        #pragma unroll
        for (int kk = 0; kk < 16; kk++){
            float a[4];
            #pragma unroll
            for (int q = 0; q < 4; q++) a[q] = As[kk][ty*4+q];
            float4 b0 = *(const float4*)&Bs[kk][tx*8];
            float4 b1 = *(const float4*)&Bs[kk][tx*8+4];
            #pragma unroll
            for (int q = 0; q < 4; q++){
                acc[q][0]+=a[q]*b0.x; acc[q][1]+=a[q]*b0.y; acc[q][2]+=a[q]*b0.z; acc[q][3]+=a[q]*b0.w;
                acc[q][4]+=a[q]*b1.x; acc[q][5]+=a[q]*b1.y; acc[q][6]+=a[q]*b1.z; acc[q][7]+=a[q]*b1.w;
            }
        }
        __syncthreads();
    }
    #pragma unroll
    for (int q = 0; q < 4; q++){
        int row = row0 + ty*4 + q;
        #pragma unroll
        for (int j = 0; j < 8; j++){
            int n = tx*8 + j;
            g_hproj[row*HH + n] = acc[q][j] + ddb[step*128 + n];
        }
    }
}

// ---------------- decoder temporal attention scores, 128x128 tile ----------------
__global__ void dattn_kernel(const float* __restrict__ ddw, const float* __restrict__ dlw,
                             const float* __restrict__ dlb, int step){
    __shared__ float sA[16][129];
    __shared__ float sB[16][128];
    __shared__ float sdl[128];
    __shared__ float red[128][17];
    int tid = threadIdx.x, tx = tid & 15, ty = tid >> 4;
    int row0 = blockIdx.x * 128;
    if (tid < 128) sdl[tid] = dlw[step*128 + tid];
    const float* W = ddw + step*256*128;
    float acc[8][8] = {};
    for (int k0 = 0; k0 < 128; k0 += 16){
        for (int i = tid; i < 128*16; i += 256){
            int m = i >> 4, k = i & 15;
            sA[k][m] = g_enc[(row0+m)*HH + k0 + k];
        }
        for (int i = tid; i < 16*128; i += 256){
            int k = i >> 7, n = i & 127;
            sB[k][n] = W[(k0+k)*128 + n];
        }
        __syncthreads();
        #pragma unroll
        for (int kk = 0; kk < 16; kk++){
            float a[8];
            #pragma unroll
            for (int q = 0; q < 8; q++) a[q] = sA[kk][ty*8+q];
            float4 b0 = *(const float4*)&sB[kk][tx*8];
            float4 b1 = *(const float4*)&sB[kk][tx*8+4];
            #pragma unroll
            for (int q = 0; q < 8; q++){
                acc[q][0]+=a[q]*b0.x; acc[q][1]+=a[q]*b0.y; acc[q][2]+=a[q]*b0.z; acc[q][3]+=a[q]*b0.w;
                acc[q][4]+=a[q]*b1.x; acc[q][5]+=a[q]*b1.y; acc[q][6]+=a[q]*b1.z; acc[q][7]+=a[q]*b1.w;
            }
        }
        __syncthreads();
    }
    #pragma unroll
    for (int q = 0; q < 8; q++){
        int row = row0 + ty*8 + q;
        int bb = row / LL;
        float p = 0.f;
        #pragma unroll
        for (int j = 0; j < 8; j++){
            int n = tx*8 + j;
            p += tanhf(acc[q][j] + g_hproj[bb*HH + n]) * sdl[n];
        }
        red[ty*8+q][tx] = p;
    }
    __syncthreads();
    if (tid < 128){
        float s = 0.f;
        #pragma unroll
        for (int xk = 0; xk < 16; xk++) s += red[tid][xk];
        g_e2[row0 + tid] = s + dlb[step];
    }
}

// ---------------- softmax over L + context ----------------
__global__ void softctx_kernel(){
    __shared__ float sal[LL];
    __shared__ float sinv;
    int b = blockIdx.x, tid = threadIdx.x;  // 128 threads
    if (tid < LL) sal[tid] = g_e2[b*LL + tid];
    __syncthreads();
    if (tid == 0){
        float mx = -1e30f;
        for (int l = 0; l < LL; l++) mx = fmaxf(mx, sal[l]);
        float s = 0.f;
        for (int l = 0; l < LL; l++){ float e = __expf(sal[l]-mx); sal[l]=e; s+=e; }
        sinv = 1.f/s;
    }
    __syncthreads();
    float a = 0.f;
    #pragma unroll 5
    for (int l = 0; l < LL; l++) a += sal[l]*g_enc[(b*LL + l)*HH + tid];
    g_ctx[b*HH + tid] = a*sinv;
}

// ---------------- output head ----------------
__global__ void head_kernel(const float* __restrict__ fcw, const float* __restrict__ fcb,
                            const float* __restrict__ ow,  const float* __restrict__ ob,
                            float* __restrict__ out, int step){
    __shared__ float sh[128];
    __shared__ float sp[2];
    int b = blockIdx.x, tid = threadIdx.x;  // 64 threads
    sh[tid]      = g_hde[b*HH + tid];
    sh[tid + 64] = g_hde[b*HH + 64 + tid];
    __syncthreads();
    float s = fcb[step*64 + tid];
    const float* W = fcw + step*HH*64;
    #pragma unroll 8
    for (int k = 0; k < 128; k++) s += sh[k]*W[k*64 + tid];
    float y = tanhf(s)*ow[step*64 + tid];
    #pragma unroll
    for (int off = 16; off; off >>= 1) y += __shfl_down_sync(0xffffffffu, y, off);
    if ((tid & 31) == 0) sp[tid >> 5] = y;
    __syncthreads();
    if (tid == 0){
        float r = sp[0] + sp[1] + ob[step];
        out[b*NOUTS + step] = 1.f/(1.f + __expf(-r));
    }
}

// ---------------- launcher ----------------
extern "C" void kernel_launch(void* const* d_in, const int* in_sizes, int n_in,
                              void* d_out, int out_size){
    const float* x     = (const float*)d_in[0];
    const float* eWih  = (const float*)d_in[1];
    const float* eWhh  = (const float*)d_in[2];
    const float* ebih  = (const float*)d_in[3];
    const float* ebhh  = (const float*)d_in[4];
    const float* attw  = (const float*)d_in[5];
    const float* attb  = (const float*)d_in[6];
    const float* dWih  = (const float*)d_in[7];
    const float* dWhh  = (const float*)d_in[8];
    const float* dbih  = (const float*)d_in[9];
    const float* dbhh  = (const float*)d_in[10];
    const float* ddw   = (const float*)d_in[11];
    const float* ddb   = (const float*)d_in[12];
    const float* dlw   = (const float*)d_in[13];
    const float* dlb   = (const float*)d_in[14];
    const float* fcw   = (const float*)d_in[15];
    const float* fcb   = (const float*)d_in[16];
    const float* ow    = (const float*)d_in[17];
    const float* ob    = (const float*)d_in[18];
    float* out = (float*)d_out;

    const int ENC_SMEM = (3264 + 1024 + 16384) * 4;  // 82688
    const int DEC_SMEM = (6528 + 16384) * 4;          // 91648
    cudaFuncSetAttribute(enc_step_kernel, cudaFuncAttributeMaxDynamicSharedMemorySize, ENC_SMEM);
    cudaFuncSetAttribute(dec_step_kernel, cudaFuncAttributeMaxDynamicSharedMemorySize, DEC_SMEM);

    zero_kernel<<<(BB*HH + 255)/256, 256>>>();
    prep_kernel<<<(KDEC*G4 + 255)/256, 256>>>(eWih, eWhh, ebih, ebhh, dWih, dWhh, dbih, dbhh);

    for (int t = 0; t < LL; t++){
        enc_step_kernel<<<BB/16, 256, ENC_SMEM>>>(x, attw, attb, t);
    }

    for (int i = 0; i < NOUTS; i++){
        hproj_kernel<<<BB/64, 256>>>(ddw, ddb, i);
        dattn_kernel<<<(BB*LL)/128, 256>>>(ddw, dlw, dlb, i);
        softctx_kernel<<<BB, 128>>>();
        dec_step_kernel<<<BB/16, 256, DEC_SMEM>>>();
        head_kernel<<<BB, 64>>>(fcw, fcb, ow, ob, out, i);
    }
}

// round 5
// speedup vs baseline: 2.0376x; 1.4284x over previous
#include <cuda_runtime.h>
#include <cstdint>
#include <math.h>

#define BB 2048
#define LL 50
#define FF 64
#define HH 128
#define NOUTS 3
#define G4 512   // 4*H
#define KENC 192 // F + H
#define KDEC 384 // 2H + H

// ---------------- scratch (static device allocations only) ----------------
__device__ float g_h[BB*HH];
__device__ float g_c[BB*HH];
__device__ float g_hde[BB*HH];
__device__ float g_cde[BB*HH];
__device__ float g_enc[BB*LL*HH];
__device__ float g_ctx[BB*HH];
__device__ float g_hproj[BB*HH];
__device__ float g_e2[BB*LL];
// packed weights: [half][k][nl*4 + gate], col = gate*128 + half*64 + nl
__device__ float g_WencP[2*KENC*256];
__device__ float g_WdecP[2*KDEC*256];
__device__ float g_bencP[512];
__device__ float g_bdecP[512];

__device__ __forceinline__ float sigf(float v){ return 1.f/(1.f+__expf(-v)); }

__device__ __forceinline__ void cp16(void* dst, const void* src){
    unsigned int d = (unsigned int)__cvta_generic_to_shared(dst);
    asm volatile("cp.async.ca.shared.global [%0], [%1], 16;" :: "r"(d), "l"(src));
}
__device__ __forceinline__ void cp_commit(){ asm volatile("cp.async.commit_group;"); }
__device__ __forceinline__ void cp_wait1(){ asm volatile("cp.async.wait_group 1;"); }
__device__ __forceinline__ void cp_wait0(){ asm volatile("cp.async.wait_group 0;"); }

// ---------------- init / weight prep ----------------
__global__ void zero_kernel(){
    int idx = blockIdx.x*256 + threadIdx.x;
    if (idx < BB*HH){ g_h[idx]=0.f; g_c[idx]=0.f; g_hde[idx]=0.f; g_cde[idx]=0.f; }
}

__global__ void prep_kernel(const float* __restrict__ eWih, const float* __restrict__ eWhh,
                            const float* __restrict__ ebih, const float* __restrict__ ebhh,
                            const float* __restrict__ dWih, const float* __restrict__ dWhh,
                            const float* __restrict__ dbih, const float* __restrict__ dbhh){
    int idx = blockIdx.x*256 + threadIdx.x;
    if (idx < 2*KENC*256){
        int half = idx / (KENC*256);
        int rem  = idx % (KENC*256);
        int k = rem >> 8, r = rem & 255;
        int nl = r >> 2, g = r & 3;
        int n = g*128 + half*64 + nl;
        g_WencP[idx] = (k < FF) ? eWih[n*FF + k] : eWhh[n*HH + (k - FF)];
    }
    if (idx < 2*KDEC*256){
        int half = idx / (KDEC*256);
        int rem  = idx % (KDEC*256);
        int k = rem >> 8, r = rem & 255;
        int nl = r >> 2, g = r & 3;
        int n = g*128 + half*64 + nl;
        g_WdecP[idx] = (k < 256) ? dWih[n*256 + k] : dWhh[n*HH + (k - 256)];
    }
    if (idx < 512){
        int half = idx >> 8, r = idx & 255;
        int nl = r >> 2, g = r & 3;
        int n = g*128 + half*64 + nl;
        g_bencP[idx] = ebih[n] + ebhh[n];
        g_bdecP[idx] = dbih[n] + dbhh[n];
    }
}

// =======================================================================
// FUSED ENCODER STEP v2: grid (2 n-halves, 128 row-tiles), 256 threads.
// Shared: sAT[192*17] + sE[16*64] + sB[2][32*256]  (~82.7 KB, 2 blocks/SM)
// =======================================================================
__global__ void enc_step_kernel(const float* __restrict__ x,
                                const float* __restrict__ aw,
                                const float* __restrict__ ab, int t){
    extern __shared__ float sm[];
    float* sAT = sm;                  // 3264
    float* sE  = sm + 3264;           // 1024
    float* sB  = sm + 4288;           // 16384 (2 x 32x256)
    int tid = threadIdx.x;
    int half = blockIdx.x;
    int row0 = blockIdx.y * 16;

    // load x_t rows (feature-major) and h rows into sAT
    for (int i = tid; i < 16*64; i += 256){
        int m = i >> 6, f = i & 63;
        sAT[f*17 + m] = x[((row0+m)*LL + t)*FF + f];
    }
    for (int i = tid; i < 16*128; i += 256){
        int m = i >> 7, k = i & 127;
        sAT[(64+k)*17 + m] = g_h[(row0+m)*HH + k];
    }
    __syncthreads();

    // ---- phase 1: e = tanh([x|h] @ aw_t + ab_t), weights direct from global ----
    {
        int c = tid & 63, m0 = tid >> 6;
        const float* W1 = aw + (size_t)t*KENC*FF;
        float acc[4] = {};
        #pragma unroll 8
        for (int k = 0; k < KENC; k++){
            float b = __ldg(&W1[k*FF + c]);
            #pragma unroll
            for (int q = 0; q < 4; q++)
                acc[q] += sAT[k*17 + m0 + 4*q] * b;
        }
        float bias = ab[t*FF + c];
        #pragma unroll
        for (int q = 0; q < 4; q++)
            sE[(m0+4*q)*64 + c] = tanhf(acc[q] + bias);
    }
    __syncthreads();

    // ---- softmax over 64 features, xin = prob * x (in place in sAT) ----
    {
        int wid = tid >> 5, lane = tid & 31;
        #pragma unroll
        for (int rr = 0; rr < 2; rr++){
            int r = wid*2 + rr;
            float v0 = sE[r*64 + lane], v1 = sE[r*64 + 32 + lane];
            float mx = fmaxf(v0, v1);
            #pragma unroll
            for (int off = 16; off; off >>= 1) mx = fmaxf(mx, __shfl_xor_sync(0xffffffffu, mx, off));
            float e0 = __expf(v0 - mx), e1 = __expf(v1 - mx);
            float s = e0 + e1;
            #pragma unroll
            for (int off = 16; off; off >>= 1) s += __shfl_xor_sync(0xffffffffu, s, off);
            float inv = 1.f/s;
            sAT[lane*17 + r]      *= e0*inv;
            sAT[(lane+32)*17 + r] *= e1*inv;
        }
    }
    __syncthreads();

    // ---- phase 2: gate GEMM with cp.async double-buffered B slabs ----
    int tx = tid & 63, ty = tid >> 6;
    const float* Wp = g_WencP + half*(KENC*256);
    // preload slab 0
    {
        float* dst = sB;
        const float* src = Wp;
        #pragma unroll
        for (int i = tid*4; i < 8192; i += 1024) cp16(dst + i, src + i);
        cp_commit();
    }
    float acc[4][4] = {};
    #pragma unroll 1
    for (int s = 0; s < 6; s++){
        if (s < 5){
            float* dst = sB + ((s+1)&1)*8192;
            const float* src = Wp + (s+1)*8192;
            #pragma unroll
            for (int i = tid*4; i < 8192; i += 1024) cp16(dst + i, src + i);
            cp_commit();
            cp_wait1();
        } else {
            cp_wait0();
        }
        __syncthreads();
        const float* Bf = sB + (s&1)*8192;
        #pragma unroll
        for (int kk = 0; kk < 32; kk++){
            int k = s*32 + kk;
            float a[4];
            #pragma unroll
            for (int q = 0; q < 4; q++) a[q] = sAT[k*17 + ty*4 + q];
            float4 b = *(const float4*)&Bf[kk*256 + tx*4];
            #pragma unroll
            for (int q = 0; q < 4; q++){
                acc[q][0] += a[q]*b.x; acc[q][1] += a[q]*b.y;
                acc[q][2] += a[q]*b.z; acc[q][3] += a[q]*b.w;
            }
        }
        __syncthreads();
    }
    // gate epilogue (striped bias)
    {
        int n = half*64 + tx;
        const float* bP = g_bencP + half*256;
        float b0 = bP[tx*4+0], b1 = bP[tx*4+1], b2 = bP[tx*4+2], b3 = bP[tx*4+3];
        #pragma unroll
        for (int q = 0; q < 4; q++){
            int row = row0 + ty*4 + q;
            float ig = sigf (acc[q][0] + b0);
            float fg = sigf (acc[q][1] + b1);
            float gg = tanhf(acc[q][2] + b2);
            float og = sigf (acc[q][3] + b3);
            float cn = fg*g_c[row*HH + n] + ig*gg;
            g_c[row*HH + n] = cn;
            float h = og*tanhf(cn);
            g_h[row*HH + n] = h;
            g_enc[(row*LL + t)*HH + n] = h;
        }
    }
}

// =======================================================================
// FUSED DECODER LSTM STEP v2: grid (2, 128), cp.async pipeline, K=384
// =======================================================================
__global__ void dec_step_kernel(){
    extern __shared__ float sm[];
    float* sAT = sm;                  // 384*17 = 6528
    float* sB  = sm + 6528;           // 16384
    int tid = threadIdx.x;
    int half = blockIdx.x;
    int row0 = blockIdx.y * 16;

    for (int i = tid; i < 16*128; i += 256){
        int m = i >> 7, k = i & 127;
        float ctx = g_ctx[(row0+m)*HH + k];
        float h   = g_hde[(row0+m)*HH + k];
        sAT[k*17 + m]       = ctx;
        sAT[(128+k)*17 + m] = h;
        sAT[(256+k)*17 + m] = h;
    }
    int tx = tid & 63, ty = tid >> 6;
    const float* Wp = g_WdecP + half*(KDEC*256);
    {
        float* dst = sB;
        const float* src = Wp;
        #pragma unroll
        for (int i = tid*4; i < 8192; i += 1024) cp16(dst + i, src + i);
        cp_commit();
    }
    __syncthreads();
    float acc[4][4] = {};
    #pragma unroll 1
    for (int s = 0; s < 12; s++){
        if (s < 11){
            float* dst = sB + ((s+1)&1)*8192;
            const float* src = Wp + (s+1)*8192;
            #pragma unroll
            for (int i = tid*4; i < 8192; i += 1024) cp16(dst + i, src + i);
            cp_commit();
            cp_wait1();
        } else {
            cp_wait0();
        }
        __syncthreads();
        const float* Bf = sB + (s&1)*8192;
        #pragma unroll
        for (int kk = 0; kk < 32; kk++){
            int k = s*32 + kk;
            float a[4];
            #pragma unroll
            for (int q = 0; q < 4; q++) a[q] = sAT[k*17 + ty*4 + q];
            float4 b = *(const float4*)&Bf[kk*256 + tx*4];
            #pragma unroll
            for (int q = 0; q < 4; q++){
                acc[q][0] += a[q]*b.x; acc[q][1] += a[q]*b.y;
                acc[q][2] += a[q]*b.z; acc[q][3] += a[q]*b.w;
            }
        }
        __syncthreads();
    }
    {
        int n = half*64 + tx;
        const float* bP = g_bdecP + half*256;
        float b0 = bP[tx*4+0], b1 = bP[tx*4+1], b2 = bP[tx*4+2], b3 = bP[tx*4+3];
        #pragma unroll
        for (int q = 0; q < 4; q++){
            int row = row0 + ty*4 + q;
            float ig = sigf (acc[q][0] + b0);
            float fg = sigf (acc[q][1] + b1);
            float gg = tanhf(acc[q][2] + b2);
            float og = sigf (acc[q][3] + b3);
            float cn = fg*g_cde[row*HH + n] + ig*gg;
            g_cde[row*HH + n] = cn;
            g_hde[row*HH + n] = og*tanhf(cn);
        }
    }
}

// ---------------- decoder: hproj = h_de @ dd_w[i][128:256] + dd_b[i] ----------------
__global__ void hproj_kernel(const float* __restrict__ ddw, const float* __restrict__ ddb, int step){
    __shared__ float As[16][65];
    __shared__ float Bs[16][128];
    const float* W = ddw + step*256*128 + 128*128;
    int tid = threadIdx.x, tx = tid & 15, ty = tid >> 4;
    int row0 = blockIdx.x*64;
    float acc[4][8] = {};
    for (int k0 = 0; k0 < 128; k0 += 16){
        for (int i = tid; i < 64*16; i += 256){
            int m = i >> 4, k = i & 15, row = row0 + m;
            As[k][m] = g_hde[row*HH + k0 + k];
        }
        for (int i = tid; i < 16*128; i += 256){
            int kk = i >> 7, n = i & 127;
            Bs[kk][n] = W[(k0+kk)*128 + n];
        }
        __syncthreads();
        #pragma unroll
        for (int kk = 0; kk < 16; kk++){
            float a[4];
            #pragma unroll
            for (int q = 0; q < 4; q++) a[q] = As[kk][ty*4+q];
            float4 b0 = *(const float4*)&Bs[kk][tx*8];
            float4 b1 = *(const float4*)&Bs[kk][tx*8+4];
            #pragma unroll
            for (int q = 0; q < 4; q++){
                acc[q][0]+=a[q]*b0.x; acc[q][1]+=a[q]*b0.y; acc[q][2]+=a[q]*b0.z; acc[q][3]+=a[q]*b0.w;
                acc[q][4]+=a[q]*b1.x; acc[q][5]+=a[q]*b1.y; acc[q][6]+=a[q]*b1.z; acc[q][7]+=a[q]*b1.w;
            }
        }
        __syncthreads();
    }
    #pragma unroll
    for (int q = 0; q < 4; q++){
        int row = row0 + ty*4 + q;
        #pragma unroll
        for (int j = 0; j < 8; j++){
            int n = tx*8 + j;
            g_hproj[row*HH + n] = acc[q][j] + ddb[step*128 + n];
        }
    }
}

// ---------------- decoder temporal attention scores, 128x128 tile ----------------
__global__ void dattn_kernel(const float* __restrict__ ddw, const float* __restrict__ dlw,
                             const float* __restrict__ dlb, int step){
    __shared__ float sA[16][129];
    __shared__ float sB[16][128];
    __shared__ float sdl[128];
    __shared__ float red[128][17];
    int tid = threadIdx.x, tx = tid & 15, ty = tid >> 4;
    int row0 = blockIdx.x * 128;
    if (tid < 128) sdl[tid] = dlw[step*128 + tid];
    const float* W = ddw + step*256*128;
    float acc[8][8] = {};
    for (int k0 = 0; k0 < 128; k0 += 16){
        for (int i = tid; i < 128*16; i += 256){
            int m = i >> 4, k = i & 15;
            sA[k][m] = g_enc[(row0+m)*HH + k0 + k];
        }
        for (int i = tid; i < 16*128; i += 256){
            int k = i >> 7, n = i & 127;
            sB[k][n] = W[(k0+k)*128 + n];
        }
        __syncthreads();
        #pragma unroll
        for (int kk = 0; kk < 16; kk++){
            float a[8];
            #pragma unroll
            for (int q = 0; q < 8; q++) a[q] = sA[kk][ty*8+q];
            float4 b0 = *(const float4*)&sB[kk][tx*8];
            float4 b1 = *(const float4*)&sB[kk][tx*8+4];
            #pragma unroll
            for (int q = 0; q < 8; q++){
                acc[q][0]+=a[q]*b0.x; acc[q][1]+=a[q]*b0.y; acc[q][2]+=a[q]*b0.z; acc[q][3]+=a[q]*b0.w;
                acc[q][4]+=a[q]*b1.x; acc[q][5]+=a[q]*b1.y; acc[q][6]+=a[q]*b1.z; acc[q][7]+=a[q]*b1.w;
            }
        }
        __syncthreads();
    }
    #pragma unroll
    for (int q = 0; q < 8; q++){
        int row = row0 + ty*8 + q;
        int bb = row / LL;
        float p = 0.f;
        #pragma unroll
        for (int j = 0; j < 8; j++){
            int n = tx*8 + j;
            p += tanhf(acc[q][j] + g_hproj[bb*HH + n]) * sdl[n];
        }
        red[ty*8+q][tx] = p;
    }
    __syncthreads();
    if (tid < 128){
        float s = 0.f;
        #pragma unroll
        for (int xk = 0; xk < 16; xk++) s += red[tid][xk];
        g_e2[row0 + tid] = s + dlb[step];
    }
}

// ---------------- softmax over L + context ----------------
__global__ void softctx_kernel(){
    __shared__ float sal[LL];
    __shared__ float sinv;
    int b = blockIdx.x, tid = threadIdx.x;  // 128 threads
    if (tid < LL) sal[tid] = g_e2[b*LL + tid];
    __syncthreads();
    if (tid == 0){
        float mx = -1e30f;
        for (int l = 0; l < LL; l++) mx = fmaxf(mx, sal[l]);
        float s = 0.f;
        for (int l = 0; l < LL; l++){ float e = __expf(sal[l]-mx); sal[l]=e; s+=e; }
        sinv = 1.f/s;
    }
    __syncthreads();
    float a = 0.f;
    #pragma unroll 5
    for (int l = 0; l < LL; l++) a += sal[l]*g_enc[(b*LL + l)*HH + tid];
    g_ctx[b*HH + tid] = a*sinv;
}

// ---------------- output head ----------------
__global__ void head_kernel(const float* __restrict__ fcw, const float* __restrict__ fcb,
                            const float* __restrict__ ow,  const float* __restrict__ ob,
                            float* __restrict__ out, int step){
    __shared__ float sh[128];
    __shared__ float sp[2];
    int b = blockIdx.x, tid = threadIdx.x;  // 64 threads
    sh[tid]      = g_hde[b*HH + tid];
    sh[tid + 64] = g_hde[b*HH + 64 + tid];
    __syncthreads();
    float s = fcb[step*64 + tid];
    const float* W = fcw + step*HH*64;
    #pragma unroll 8
    for (int k = 0; k < 128; k++) s += sh[k]*W[k*64 + tid];
    float y = tanhf(s)*ow[step*64 + tid];
    #pragma unroll
    for (int off = 16; off; off >>= 1) y += __shfl_down_sync(0xffffffffu, y, off);
    if ((tid & 31) == 0) sp[tid >> 5] = y;
    __syncthreads();
    if (tid == 0){
        float r = sp[0] + sp[1] + ob[step];
        out[b*NOUTS + step] = 1.f/(1.f + __expf(-r));
    }
}

// ---------------- launcher ----------------
extern "C" void kernel_launch(void* const* d_in, const int* in_sizes, int n_in,
                              void* d_out, int out_size){
    const float* x     = (const float*)d_in[0];
    const float* eWih  = (const float*)d_in[1];
    const float* eWhh  = (const float*)d_in[2];
    const float* ebih  = (const float*)d_in[3];
    const float* ebhh  = (const float*)d_in[4];
    const float* attw  = (const float*)d_in[5];
    const float* attb  = (const float*)d_in[6];
    const float* dWih  = (const float*)d_in[7];
    const float* dWhh  = (const float*)d_in[8];
    const float* dbih  = (const float*)d_in[9];
    const float* dbhh  = (const float*)d_in[10];
    const float* ddw   = (const float*)d_in[11];
    const float* ddb   = (const float*)d_in[12];
    const float* dlw   = (const float*)d_in[13];
    const float* dlb   = (const float*)d_in[14];
    const float* fcw   = (const float*)d_in[15];
    const float* fcb   = (const float*)d_in[16];
    const float* ow    = (const float*)d_in[17];
    const float* ob    = (const float*)d_in[18];
    float* out = (float*)d_out;

    const int ENC_SMEM = (3264 + 1024 + 16384) * 4;  // 82,688 B
    const int DEC_SMEM = (6528 + 16384) * 4;          // 91,648 B
    cudaFuncSetAttribute(enc_step_kernel, cudaFuncAttributeMaxDynamicSharedMemorySize, ENC_SMEM);
    cudaFuncSetAttribute(dec_step_kernel, cudaFuncAttributeMaxDynamicSharedMemorySize, DEC_SMEM);

    zero_kernel<<<(BB*HH + 255)/256, 256>>>();
    prep_kernel<<<(2*KDEC*256 + 255)/256, 256>>>(eWih, eWhh, ebih, ebhh, dWih, dWhh, dbih, dbhh);

    for (int t = 0; t < LL; t++){
        enc_step_kernel<<<dim3(2, BB/16), 256, ENC_SMEM>>>(x, attw, attb, t);
    }

    for (int i = 0; i < NOUTS; i++){
        hproj_kernel<<<BB/64, 256>>>(ddw, ddb, i);
        dattn_kernel<<<(BB*LL)/128, 256>>>(ddw, dlw, dlb, i);
        softctx_kernel<<<BB, 128>>>();
        dec_step_kernel<<<dim3(2, BB/16), 256, DEC_SMEM>>>();
        head_kernel<<<BB, 64>>>(fcw, fcb, ow, ob, out, i);
    }
}

// round 6
// speedup vs baseline: 2.1153x; 1.0381x over previous
#include <cuda_runtime.h>
#include <cstdint>
#include <math.h>

#define BB 2048
#define LL 50
#define FF 64
#define HH 128
#define NOUTS 3
#define G4 512   // 4*H
#define KENC 192 // F + H
#define KDEC 384 // 2H + H

// ---------------- scratch (static device allocations only) ----------------
__device__ float g_h[BB*HH];
__device__ float g_c[BB*HH];
__device__ float g_hde[BB*HH];
__device__ float g_cde[BB*HH];
__device__ float g_enc[BB*LL*HH];
__device__ float g_ctx[BB*HH];
__device__ float g_hproj[BB*HH];
__device__ float g_e2[BB*LL];
// packed weights: [half][k][nl*4 + gate], col = gate*128 + half*64 + nl
__device__ float g_WencP[2*KENC*256];
__device__ float g_WdecP[2*KDEC*256];
__device__ float g_bencP[512];
__device__ float g_bdecP[512];

__device__ __forceinline__ float sigf(float v){ return 1.f/(1.f+__expf(-v)); }

__device__ __forceinline__ void cp16(void* dst, const void* src){
    unsigned int d = (unsigned int)__cvta_generic_to_shared(dst);
    asm volatile("cp.async.ca.shared.global [%0], [%1], 16;" :: "r"(d), "l"(src));
}
__device__ __forceinline__ void cp_commit(){ asm volatile("cp.async.commit_group;"); }
__device__ __forceinline__ void cp_wait1(){ asm volatile("cp.async.wait_group 1;"); }
__device__ __forceinline__ void cp_wait0(){ asm volatile("cp.async.wait_group 0;"); }

// ---------------- init / weight prep ----------------
__global__ void zero_kernel(){
    int idx = blockIdx.x*256 + threadIdx.x;
    if (idx < BB*HH){ g_h[idx]=0.f; g_c[idx]=0.f; g_hde[idx]=0.f; g_cde[idx]=0.f; }
}

__global__ void prep_kernel(const float* __restrict__ eWih, const float* __restrict__ eWhh,
                            const float* __restrict__ ebih, const float* __restrict__ ebhh,
                            const float* __restrict__ dWih, const float* __restrict__ dWhh,
                            const float* __restrict__ dbih, const float* __restrict__ dbhh){
    int idx = blockIdx.x*256 + threadIdx.x;
    if (idx < 2*KENC*256){
        int half = idx / (KENC*256);
        int rem  = idx % (KENC*256);
        int k = rem >> 8, r = rem & 255;
        int nl = r >> 2, g = r & 3;
        int n = g*128 + half*64 + nl;
        g_WencP[idx] = (k < FF) ? eWih[n*FF + k] : eWhh[n*HH + (k - FF)];
    }
    if (idx < 2*KDEC*256){
        int half = idx / (KDEC*256);
        int rem  = idx % (KDEC*256);
        int k = rem >> 8, r = rem & 255;
        int nl = r >> 2, g = r & 3;
        int n = g*128 + half*64 + nl;
        g_WdecP[idx] = (k < 256) ? dWih[n*256 + k] : dWhh[n*HH + (k - 256)];
    }
    if (idx < 512){
        int half = idx >> 8, r = idx & 255;
        int nl = r >> 2, g = r & 3;
        int n = g*128 + half*64 + nl;
        g_bencP[idx] = ebih[n] + ebhh[n];
        g_bdecP[idx] = dbih[n] + dbhh[n];
    }
}

// =======================================================================
// FUSED ENCODER STEP v3: grid (2 n-halves, 128 row-tiles), 256 threads.
// sAT stride 20 (LDS.128-able), BK=16 double-buffered slabs.
// Shared: sAT[192*20]=3840 + sE[1024] + sB[2*16*256]=8192 -> 52,224 B
// =======================================================================
__global__ void enc_step_kernel(const float* __restrict__ x,
                                const float* __restrict__ aw,
                                const float* __restrict__ ab, int t){
    extern __shared__ float sm[];
    float* sAT = sm;                  // 3840
    float* sE  = sm + 3840;           // 1024
    float* sB  = sm + 4864;           // 8192 (2 x 16x256)
    int tid = threadIdx.x;
    int half = blockIdx.x;
    int row0 = blockIdx.y * 16;

    // load x_t rows and h rows into sAT (coalesced global reads)
    for (int i = tid; i < 16*64; i += 256){
        int m = i >> 6, f = i & 63;
        sAT[f*20 + m] = x[((row0+m)*LL + t)*FF + f];
    }
    for (int i = tid; i < 16*128; i += 256){
        int m = i >> 7, k = i & 127;
        sAT[(64+k)*20 + m] = g_h[(row0+m)*HH + k];
    }
    __syncthreads();

    // ---- phase 1: e = tanh([x|h] @ aw_t + ab_t); A via LDS.128 ----
    {
        int c = tid & 63, m0 = tid >> 6;   // rows m0*4 .. m0*4+3
        const float* W1 = aw + (size_t)t*KENC*FF;
        float acc[4] = {};
        #pragma unroll 8
        for (int k = 0; k < KENC; k++){
            float b = __ldg(&W1[k*FF + c]);
            float4 a = *(const float4*)&sAT[k*20 + m0*4];
            acc[0] += a.x*b; acc[1] += a.y*b; acc[2] += a.z*b; acc[3] += a.w*b;
        }
        float bias = ab[t*FF + c];
        #pragma unroll
        for (int q = 0; q < 4; q++)
            sE[(m0*4+q)*64 + c] = tanhf(acc[q] + bias);
    }
    __syncthreads();

    // ---- softmax over 64 features, xin = prob * x (in place in sAT) ----
    {
        int wid = tid >> 5, lane = tid & 31;
        #pragma unroll
        for (int rr = 0; rr < 2; rr++){
            int r = wid*2 + rr;
            float v0 = sE[r*64 + lane], v1 = sE[r*64 + 32 + lane];
            float mx = fmaxf(v0, v1);
            #pragma unroll
            for (int off = 16; off; off >>= 1) mx = fmaxf(mx, __shfl_xor_sync(0xffffffffu, mx, off));
            float e0 = __expf(v0 - mx), e1 = __expf(v1 - mx);
            float s = e0 + e1;
            #pragma unroll
            for (int off = 16; off; off >>= 1) s += __shfl_xor_sync(0xffffffffu, s, off);
            float inv = 1.f/s;
            sAT[lane*20 + r]      *= e0*inv;
            sAT[(lane+32)*20 + r] *= e1*inv;
        }
    }
    __syncthreads();

    // ---- phase 2: gate GEMM, BK=16 double-buffered cp.async slabs ----
    int tx = tid & 63, ty = tid >> 6;     // rows ty*4..ty*4+3
    const float* Wp = g_WencP + half*(KENC*256);
    {
        #pragma unroll
        for (int i = tid*4; i < 4096; i += 1024) cp16(sB + i, Wp + i);
        cp_commit();
    }
    float acc[4][4] = {};
    #pragma unroll 1
    for (int s = 0; s < 12; s++){
        if (s < 11){
            float* dst = sB + ((s+1)&1)*4096;
            const float* src = Wp + (s+1)*4096;
            #pragma unroll
            for (int i = tid*4; i < 4096; i += 1024) cp16(dst + i, src + i);
            cp_commit();
            cp_wait1();
        } else {
            cp_wait0();
        }
        __syncthreads();
        const float* Bf = sB + (s&1)*4096;
        #pragma unroll
        for (int kk = 0; kk < 16; kk++){
            int k = s*16 + kk;
            float4 a = *(const float4*)&sAT[k*20 + ty*4];
            float4 b = *(const float4*)&Bf[kk*256 + tx*4];
            acc[0][0]+=a.x*b.x; acc[0][1]+=a.x*b.y; acc[0][2]+=a.x*b.z; acc[0][3]+=a.x*b.w;
            acc[1][0]+=a.y*b.x; acc[1][1]+=a.y*b.y; acc[1][2]+=a.y*b.z; acc[1][3]+=a.y*b.w;
            acc[2][0]+=a.z*b.x; acc[2][1]+=a.z*b.y; acc[2][2]+=a.z*b.z; acc[2][3]+=a.z*b.w;
            acc[3][0]+=a.w*b.x; acc[3][1]+=a.w*b.y; acc[3][2]+=a.w*b.z; acc[3][3]+=a.w*b.w;
        }
        __syncthreads();
    }
    // gate epilogue (striped bias)
    {
        int n = half*64 + tx;
        const float* bP = g_bencP + half*256;
        float b0 = bP[tx*4+0], b1 = bP[tx*4+1], b2 = bP[tx*4+2], b3 = bP[tx*4+3];
        #pragma unroll
        for (int q = 0; q < 4; q++){
            int row = row0 + ty*4 + q;
            float ig = sigf (acc[q][0] + b0);
            float fg = sigf (acc[q][1] + b1);
            float gg = tanhf(acc[q][2] + b2);
            float og = sigf (acc[q][3] + b3);
            float cn = fg*g_c[row*HH + n] + ig*gg;
            g_c[row*HH + n] = cn;
            float h = og*tanhf(cn);
            g_h[row*HH + n] = h;
            g_enc[(row*LL + t)*HH + n] = h;
        }
    }
}

// =======================================================================
// FUSED DECODER LSTM STEP v3: grid (2, 128), BK=16 pipeline, K=384
// Shared: sAT[384*20]=7680 + sB[8192] -> 63,488 B
// =======================================================================
__global__ void dec_step_kernel(){
    extern __shared__ float sm[];
    float* sAT = sm;                  // 7680
    float* sB  = sm + 7680;           // 8192
    int tid = threadIdx.x;
    int half = blockIdx.x;
    int row0 = blockIdx.y * 16;

    for (int i = tid; i < 16*128; i += 256){
        int m = i >> 7, k = i & 127;
        float ctx = g_ctx[(row0+m)*HH + k];
        float h   = g_hde[(row0+m)*HH + k];
        sAT[k*20 + m]       = ctx;
        sAT[(128+k)*20 + m] = h;
        sAT[(256+k)*20 + m] = h;
    }
    int tx = tid & 63, ty = tid >> 6;
    const float* Wp = g_WdecP + half*(KDEC*256);
    {
        #pragma unroll
        for (int i = tid*4; i < 4096; i += 1024) cp16(sB + i, Wp + i);
        cp_commit();
    }
    __syncthreads();
    float acc[4][4] = {};
    #pragma unroll 1
    for (int s = 0; s < 24; s++){
        if (s < 23){
            float* dst = sB + ((s+1)&1)*4096;
            const float* src = Wp + (s+1)*4096;
            #pragma unroll
            for (int i = tid*4; i < 4096; i += 1024) cp16(dst + i, src + i);
            cp_commit();
            cp_wait1();
        } else {
            cp_wait0();
        }
        __syncthreads();
        const float* Bf = sB + (s&1)*4096;
        #pragma unroll
        for (int kk = 0; kk < 16; kk++){
            int k = s*16 + kk;
            float4 a = *(const float4*)&sAT[k*20 + ty*4];
            float4 b = *(const float4*)&Bf[kk*256 + tx*4];
            acc[0][0]+=a.x*b.x; acc[0][1]+=a.x*b.y; acc[0][2]+=a.x*b.z; acc[0][3]+=a.x*b.w;
            acc[1][0]+=a.y*b.x; acc[1][1]+=a.y*b.y; acc[1][2]+=a.y*b.z; acc[1][3]+=a.y*b.w;
            acc[2][0]+=a.z*b.x; acc[2][1]+=a.z*b.y; acc[2][2]+=a.z*b.z; acc[2][3]+=a.z*b.w;
            acc[3][0]+=a.w*b.x; acc[3][1]+=a.w*b.y; acc[3][2]+=a.w*b.z; acc[3][3]+=a.w*b.w;
        }
        __syncthreads();
    }
    {
        int n = half*64 + tx;
        const float* bP = g_bdecP + half*256;
        float b0 = bP[tx*4+0], b1 = bP[tx*4+1], b2 = bP[tx*4+2], b3 = bP[tx*4+3];
        #pragma unroll
        for (int q = 0; q < 4; q++){
            int row = row0 + ty*4 + q;
            float ig = sigf (acc[q][0] + b0);
            float fg = sigf (acc[q][1] + b1);
            float gg = tanhf(acc[q][2] + b2);
            float og = sigf (acc[q][3] + b3);
            float cn = fg*g_cde[row*HH + n] + ig*gg;
            g_cde[row*HH + n] = cn;
            g_hde[row*HH + n] = og*tanhf(cn);
        }
    }
}

// ---------------- decoder: hproj = h_de @ dd_w[i][128:256] + dd_b[i] ----------------
__global__ void hproj_kernel(const float* __restrict__ ddw, const float* __restrict__ ddb, int step){
    __shared__ float As[16][65];
    __shared__ float Bs[16][128];
    const float* W = ddw + step*256*128 + 128*128;
    int tid = threadIdx.x, tx = tid & 15, ty = tid >> 4;
    int row0 = blockIdx.x*64;
    float acc[4][8] = {};
    for (int k0 = 0; k0 < 128; k0 += 16){
        for (int i = tid; i < 64*16; i += 256){
            int m = i >> 4, k = i & 15, row = row0 + m;
            As[k][m] = g_hde[row*HH + k0 + k];
        }
        for (int i = tid; i < 16*128; i += 256){
            int kk = i >> 7, n = i & 127;
            Bs[kk][n] = W[(k0+kk)*128 + n];
        }
        __syncthreads();
        #pragma unroll
        for (int kk = 0; kk < 16; kk++){
            float a[4];
            #pragma unroll
            for (int q = 0; q < 4; q++) a[q] = As[kk][ty*4+q];
            float4 b0 = *(const float4*)&Bs[kk][tx*8];
            float4 b1 = *(const float4*)&Bs[kk][tx*8+4];
            #pragma unroll
            for (int q = 0; q < 4; q++){
                acc[q][0]+=a[q]*b0.x; acc[q][1]+=a[q]*b0.y; acc[q][2]+=a[q]*b0.z; acc[q][3]+=a[q]*b0.w;
                acc[q][4]+=a[q]*b1.x; acc[q][5]+=a[q]*b1.y; acc[q][6]+=a[q]*b1.z; acc[q][7]+=a[q]*b1.w;
            }
        }
        __syncthreads();
    }
    #pragma unroll
    for (int q = 0; q < 4; q++){
        int row = row0 + ty*4 + q;
        #pragma unroll
        for (int j = 0; j < 8; j++){
            int n = tx*8 + j;
            g_hproj[row*HH + n] = acc[q][j] + ddb[step*128 + n];
        }
    }
}

// ---------------- decoder temporal attention scores, 128x128 tile ----------------
__global__ void dattn_kernel(const float* __restrict__ ddw, const float* __restrict__ dlw,
                             const float* __restrict__ dlb, int step){
    __shared__ float sA[16*136];
    __shared__ float sB[16][128];
    __shared__ float sdl[128];
    __shared__ float red[128][17];
    int tid = threadIdx.x, tx = tid & 15, ty = tid >> 4;
    int row0 = blockIdx.x * 128;
    if (tid < 128) sdl[tid] = dlw[step*128 + tid];
    const float* W = ddw + step*256*128;
    float acc[8][8] = {};
    for (int k0 = 0; k0 < 128; k0 += 16){
        for (int i = tid; i < 128*16; i += 256){
            int m = i >> 4, k = i & 15;
            sA[k*136 + m] = g_enc[(row0+m)*HH + k0 + k];
        }
        for (int i = tid; i < 16*128; i += 256){
            int k = i >> 7, n = i & 127;
            sB[k][n] = W[(k0+k)*128 + n];
        }
        __syncthreads();
        #pragma unroll
        for (int kk = 0; kk < 16; kk++){
            float4 a0 = *(const float4*)&sA[kk*136 + ty*8];
            float4 a1 = *(const float4*)&sA[kk*136 + ty*8 + 4];
            float a[8] = {a0.x,a0.y,a0.z,a0.w,a1.x,a1.y,a1.z,a1.w};
            float4 b0 = *(const float4*)&sB[kk][tx*8];
            float4 b1 = *(const float4*)&sB[kk][tx*8+4];
            #pragma unroll
            for (int q = 0; q < 8; q++){
                acc[q][0]+=a[q]*b0.x; acc[q][1]+=a[q]*b0.y; acc[q][2]+=a[q]*b0.z; acc[q][3]+=a[q]*b0.w;
                acc[q][4]+=a[q]*b1.x; acc[q][5]+=a[q]*b1.y; acc[q][6]+=a[q]*b1.z; acc[q][7]+=a[q]*b1.w;
            }
        }
        __syncthreads();
    }
    #pragma unroll
    for (int q = 0; q < 8; q++){
        int row = row0 + ty*8 + q;
        int bb = row / LL;
        float p = 0.f;
        #pragma unroll
        for (int j = 0; j < 8; j++){
            int n = tx*8 + j;
            p += tanhf(acc[q][j] + g_hproj[bb*HH + n]) * sdl[n];
        }
        red[ty*8+q][tx] = p;
    }
    __syncthreads();
    if (tid < 128){
        float s = 0.f;
        #pragma unroll
        for (int xk = 0; xk < 16; xk++) s += red[tid][xk];
        g_e2[row0 + tid] = s + dlb[step];
    }
}

// ---------------- softmax over L + context ----------------
__global__ void softctx_kernel(){
    __shared__ float sal[LL];
    __shared__ float sinv;
    int b = blockIdx.x, tid = threadIdx.x;  // 128 threads
    if (tid < LL) sal[tid] = g_e2[b*LL + tid];
    __syncthreads();
    if (tid == 0){
        float mx = -1e30f;
        for (int l = 0; l < LL; l++) mx = fmaxf(mx, sal[l]);
        float s = 0.f;
        for (int l = 0; l < LL; l++){ float e = __expf(sal[l]-mx); sal[l]=e; s+=e; }
        sinv = 1.f/s;
    }
    __syncthreads();
    float a = 0.f;
    #pragma unroll 5
    for (int l = 0; l < LL; l++) a += sal[l]*g_enc[(b*LL + l)*HH + tid];
    g_ctx[b*HH + tid] = a*sinv;
}

// ---------------- output head ----------------
__global__ void head_kernel(const float* __restrict__ fcw, const float* __restrict__ fcb,
                            const float* __restrict__ ow,  const float* __restrict__ ob,
                            float* __restrict__ out, int step){
    __shared__ float sh[128];
    __shared__ float sp[2];
    int b = blockIdx.x, tid = threadIdx.x;  // 64 threads
    sh[tid]      = g_hde[b*HH + tid];
    sh[tid + 64] = g_hde[b*HH + 64 + tid];
    __syncthreads();
    float s = fcb[step*64 + tid];
    const float* W = fcw + step*HH*64;
    #pragma unroll 8
    for (int k = 0; k < 128; k++) s += sh[k]*W[k*64 + tid];
    float y = tanhf(s)*ow[step*64 + tid];
    #pragma unroll
    for (int off = 16; off; off >>= 1) y += __shfl_down_sync(0xffffffffu, y, off);
    if ((tid & 31) == 0) sp[tid >> 5] = y;
    __syncthreads();
    if (tid == 0){
        float r = sp[0] + sp[1] + ob[step];
        out[b*NOUTS + step] = 1.f/(1.f + __expf(-r));
    }
}

// ---------------- launcher ----------------
extern "C" void kernel_launch(void* const* d_in, const int* in_sizes, int n_in,
                              void* d_out, int out_size){
    const float* x     = (const float*)d_in[0];
    const float* eWih  = (const float*)d_in[1];
    const float* eWhh  = (const float*)d_in[2];
    const float* ebih  = (const float*)d_in[3];
    const float* ebhh  = (const float*)d_in[4];
    const float* attw  = (const float*)d_in[5];
    const float* attb  = (const float*)d_in[6];
    const float* dWih  = (const float*)d_in[7];
    const float* dWhh  = (const float*)d_in[8];
    const float* dbih  = (const float*)d_in[9];
    const float* dbhh  = (const float*)d_in[10];
    const float* ddw   = (const float*)d_in[11];
    const float* ddb   = (const float*)d_in[12];
    const float* dlw   = (const float*)d_in[13];
    const float* dlb   = (const float*)d_in[14];
    const float* fcw   = (const float*)d_in[15];
    const float* fcb   = (const float*)d_in[16];
    const float* ow    = (const float*)d_in[17];
    const float* ob    = (const float*)d_in[18];
    float* out = (float*)d_out;

    const int ENC_SMEM = (3840 + 1024 + 8192) * 4;   // 52,224 B
    const int DEC_SMEM = (7680 + 8192) * 4;           // 63,488 B
    cudaFuncSetAttribute(enc_step_kernel, cudaFuncAttributeMaxDynamicSharedMemorySize, ENC_SMEM);
    cudaFuncSetAttribute(dec_step_kernel, cudaFuncAttributeMaxDynamicSharedMemorySize, DEC_SMEM);

    zero_kernel<<<(BB*HH + 255)/256, 256>>>();
    prep_kernel<<<(2*KDEC*256 + 255)/256, 256>>>(eWih, eWhh, ebih, ebhh, dWih, dWhh, dbih, dbhh);

    for (int t = 0; t < LL; t++){
        enc_step_kernel<<<dim3(2, BB/16), 256, ENC_SMEM>>>(x, attw, attb, t);
    }

    for (int i = 0; i < NOUTS; i++){
        hproj_kernel<<<BB/64, 256>>>(ddw, ddb, i);
        dattn_kernel<<<(BB*LL)/128, 256>>>(ddw, dlw, dlb, i);
        softctx_kernel<<<BB, 128>>>();
        dec_step_kernel<<<dim3(2, BB/16), 256, DEC_SMEM>>>();
        head_kernel<<<BB, 64>>>(fcw, fcb, ow, ob, out, i);
    }
}

// round 7
// speedup vs baseline: 2.4545x; 1.1604x over previous
#include <cuda_runtime.h>
#include <cstdint>
#include <math.h>

#define BB 2048
#define LL 50
#define FF 64
#define HH 128
#define NOUTS 3
#define G4 512   // 4*H
#define KENC 192 // F + H
#define KDEC 384 // 2H + H
#define BM 8     // rows per encoder block

// ---------------- scratch (static device allocations only) ----------------
__device__ float g_hde[BB*HH];
__device__ float g_cde[BB*HH];
__device__ float g_enc[BB*LL*HH];
__device__ float g_ctx[BB*HH];
__device__ float g_hproj[BB*HH];
__device__ float g_e2[BB*LL];
// encoder packed weights (full width): [k][nc*4 + gate], n = gate*128 + nc
__device__ float g_WencF[KENC*G4];
__device__ float g_bencF[G4];
// decoder packed weights (halved): [half][k][nl*4 + gate], n = gate*128 + half*64 + nl
__device__ float g_WdecP[2*KDEC*256];
__device__ float g_bdecP[512];

__device__ __forceinline__ float sigf(float v){ return 1.f/(1.f+__expf(-v)); }

__device__ __forceinline__ void cp16(void* dst, const void* src){
    unsigned int d = (unsigned int)__cvta_generic_to_shared(dst);
    asm volatile("cp.async.ca.shared.global [%0], [%1], 16;" :: "r"(d), "l"(src));
}
__device__ __forceinline__ void cp_commit(){ asm volatile("cp.async.commit_group;"); }
__device__ __forceinline__ void cp_wait1(){ asm volatile("cp.async.wait_group 1;"); }
__device__ __forceinline__ void cp_wait0(){ asm volatile("cp.async.wait_group 0;"); }

// ---------------- init / weight prep ----------------
__global__ void zero_kernel(){
    int idx = blockIdx.x*256 + threadIdx.x;
    if (idx < BB*HH){ g_hde[idx]=0.f; g_cde[idx]=0.f; }
}

__global__ void prep_kernel(const float* __restrict__ eWih, const float* __restrict__ eWhh,
                            const float* __restrict__ ebih, const float* __restrict__ ebhh,
                            const float* __restrict__ dWih, const float* __restrict__ dWhh,
                            const float* __restrict__ dbih, const float* __restrict__ dbhh){
    int idx = blockIdx.x*256 + threadIdx.x;
    if (idx < KENC*G4){
        int k = idx >> 9, c = idx & 511;
        int nc = c >> 2, g = c & 3;
        int n = g*128 + nc;
        g_WencF[idx] = (k < FF) ? eWih[n*FF + k] : eWhh[n*HH + (k - FF)];
    }
    if (idx < 2*KDEC*256){
        int half = idx / (KDEC*256);
        int rem  = idx % (KDEC*256);
        int k = rem >> 8, r = rem & 255;
        int nl = r >> 2, g = r & 3;
        int n = g*128 + half*64 + nl;
        g_WdecP[idx] = (k < 256) ? dWih[n*256 + k] : dWhh[n*HH + (k - 256)];
    }
    if (idx < 512){
        int nc = idx >> 2, g = idx & 3;
        int n = g*128 + nc;
        g_bencF[idx] = ebih[n] + ebhh[n];
        int half = idx >> 8, r = idx & 255;
        int nl2 = r >> 2, g2 = r & 3;
        int n2 = g2*128 + half*64 + nl2;
        g_bdecP[idx] = dbih[n2] + dbhh[n2];
    }
}

// =======================================================================
// PERSISTENT ENCODER: one launch, 50 timesteps, h/c resident in smem.
// grid = 256 blocks (8 rows each), 256 threads.
// smem: sAT[192*8]=1536 | sE[512] | sC[1024] | sW[2*2048]=4096 | sB[2*8192]=16384
//       total 23552 floats = 94,208 B  (2 blocks/SM)
// =======================================================================
__global__ void enc_persist_kernel(const float* __restrict__ x,
                                   const float* __restrict__ aw,
                                   const float* __restrict__ ab){
    extern __shared__ float sm[];
    float* sAT = sm;            // [k][m] stride 8; k<64: xin, k>=64: h
    float* sE  = sm + 1536;     // 8x64
    float* sC  = sm + 2048;     // 8x128
    float* sW  = sm + 3072;     // 2 x 32x64 (phase-1 weight chunks)
    float* sB  = sm + 7168;     // 2 x 16x512 (phase-2 weight slabs)
    int tid = threadIdx.x;
    int row0 = blockIdx.x * BM;
    int txn = tid & 127, ty = tid >> 7;     // phase-2 mapping
    int c1  = tid & 63,  m0 = tid >> 6;     // phase-1 mapping

    // init h = 0, c = 0
    for (int i = tid; i < 128*BM; i += 256) sAT[512 + i] = 0.f;
    for (int i = tid; i < 128*BM; i += 256) sC[i] = 0.f;

    // hoist gate bias (constant over t)
    float4 bg = *(const float4*)&g_bencF[txn*4];
    __syncthreads();

    for (int t = 0; t < LL; t++){
        // ---- stage x_t rows into sAT[0..512) ----
        for (int i = tid; i < BM*64; i += 256){
            int m = i >> 6, f = i & 63;
            sAT[f*8 + m] = x[((row0+m)*LL + t)*FF + f];
        }
        const float* W1 = aw + (size_t)t*KENC*FF;
        // prefetch phase-1 chunk 0
        for (int i = tid*4; i < 2048; i += 1024) cp16(sW + i, W1 + i);
        cp_commit();
        __syncthreads();  // x staged; h from prev step visible

        // ---- phase 1: e = tanh([x|h] @ aw_t + ab_t), BK=32 staged chunks ----
        {
            float acc0 = 0.f, acc1 = 0.f;
            #pragma unroll 1
            for (int s = 0; s < 6; s++){
                if (s < 5){
                    float* dst = sW + ((s+1)&1)*2048;
                    const float* src = W1 + (s+1)*2048;
                    for (int i = tid*4; i < 2048; i += 1024) cp16(dst + i, src + i);
                    cp_commit(); cp_wait1();
                } else cp_wait0();
                __syncthreads();
                const float* Wf = sW + (s&1)*2048;
                #pragma unroll
                for (int kk = 0; kk < 32; kk++){
                    int k = s*32 + kk;
                    float b = Wf[kk*64 + c1];
                    float2 a = *(const float2*)&sAT[k*8 + m0*2];
                    acc0 += a.x*b; acc1 += a.y*b;
                }
                __syncthreads();
            }
            float bias = ab[t*FF + c1];
            sE[(m0*2+0)*64 + c1] = tanhf(acc0 + bias);
            sE[(m0*2+1)*64 + c1] = tanhf(acc1 + bias);
        }
        __syncthreads();

        // ---- softmax over 64 features; xin = prob * x in place ----
        {
            int w = tid >> 5, lane = tid & 31;
            float v0 = sE[w*64 + lane], v1 = sE[w*64 + 32 + lane];
            float mx = fmaxf(v0, v1);
            #pragma unroll
            for (int off = 16; off; off >>= 1) mx = fmaxf(mx, __shfl_xor_sync(0xffffffffu, mx, off));
            float e0 = __expf(v0 - mx), e1 = __expf(v1 - mx);
            float s = e0 + e1;
            #pragma unroll
            for (int off = 16; off; off >>= 1) s += __shfl_xor_sync(0xffffffffu, s, off);
            float inv = 1.f/s;
            sAT[lane*8 + w]      *= e0*inv;
            sAT[(lane+32)*8 + w] *= e1*inv;
        }
        __syncthreads();

        // ---- phase 2: gate GEMM [8 x 512 x 192], BK=16 cp.async slabs ----
        for (int i = tid*4; i < 8192; i += 1024) cp16(sB + i, g_WencF + i);
        cp_commit();
        float acc[4][4] = {};
        #pragma unroll 1
        for (int s = 0; s < 12; s++){
            if (s < 11){
                float* dst = sB + ((s+1)&1)*8192;
                const float* src = g_WencF + (s+1)*8192;
                for (int i = tid*4; i < 8192; i += 1024) cp16(dst + i, src + i);
                cp_commit(); cp_wait1();
            } else cp_wait0();
            __syncthreads();
            const float* Bf = sB + (s&1)*8192;
            #pragma unroll
            for (int kk = 0; kk < 16; kk++){
                int k = s*16 + kk;
                float4 a = *(const float4*)&sAT[k*8 + ty*4];
                float4 b = *(const float4*)&Bf[kk*512 + txn*4];
                acc[0][0]+=a.x*b.x; acc[0][1]+=a.x*b.y; acc[0][2]+=a.x*b.z; acc[0][3]+=a.x*b.w;
                acc[1][0]+=a.y*b.x; acc[1][1]+=a.y*b.y; acc[1][2]+=a.y*b.z; acc[1][3]+=a.y*b.w;
                acc[2][0]+=a.z*b.x; acc[2][1]+=a.z*b.y; acc[2][2]+=a.z*b.z; acc[2][3]+=a.z*b.w;
                acc[3][0]+=a.w*b.x; acc[3][1]+=a.w*b.y; acc[3][2]+=a.w*b.z; acc[3][3]+=a.w*b.w;
            }
            __syncthreads();
        }

        // ---- gate epilogue: update c (smem), h (smem), emit g_enc ----
        #pragma unroll
        for (int q = 0; q < 4; q++){
            int ml = ty*4 + q;
            float ig = sigf (acc[q][0] + bg.x);
            float fg = sigf (acc[q][1] + bg.y);
            float gg = tanhf(acc[q][2] + bg.z);
            float og = sigf (acc[q][3] + bg.w);
            float cn = fg*sC[ml*128 + txn] + ig*gg;
            sC[ml*128 + txn] = cn;
            float h = og*tanhf(cn);
            sAT[(64+txn)*8 + ml] = h;
            g_enc[((row0+ml)*LL + t)*HH + txn] = h;
        }
        // no sync needed: next x-load writes sAT[0..512) (disjoint from h region);
        // the sync after x-load orders h writes before phase 1 reads.
    }
}

// =======================================================================
// FUSED DECODER LSTM STEP: grid (2, 128), BK=16 pipeline, K=384
// =======================================================================
__global__ void dec_step_kernel(){
    extern __shared__ float sm[];
    float* sAT = sm;                  // 384*20 = 7680
    float* sB  = sm + 7680;           // 8192
    int tid = threadIdx.x;
    int half = blockIdx.x;
    int row0 = blockIdx.y * 16;

    for (int i = tid; i < 16*128; i += 256){
        int m = i >> 7, k = i & 127;
        float ctx = g_ctx[(row0+m)*HH + k];
        float h   = g_hde[(row0+m)*HH + k];
        sAT[k*20 + m]       = ctx;
        sAT[(128+k)*20 + m] = h;
        sAT[(256+k)*20 + m] = h;
    }
    int tx = tid & 63, ty = tid >> 6;
    const float* Wp = g_WdecP + half*(KDEC*256);
    {
        #pragma unroll
        for (int i = tid*4; i < 4096; i += 1024) cp16(sB + i, Wp + i);
        cp_commit();
    }
    __syncthreads();
    float acc[4][4] = {};
    #pragma unroll 1
    for (int s = 0; s < 24; s++){
        if (s < 23){
            float* dst = sB + ((s+1)&1)*4096;
            const float* src = Wp + (s+1)*4096;
            #pragma unroll
            for (int i = tid*4; i < 4096; i += 1024) cp16(dst + i, src + i);
            cp_commit();
            cp_wait1();
        } else {
            cp_wait0();
        }
        __syncthreads();
        const float* Bf = sB + (s&1)*4096;
        #pragma unroll
        for (int kk = 0; kk < 16; kk++){
            int k = s*16 + kk;
            float4 a = *(const float4*)&sAT[k*20 + ty*4];
            float4 b = *(const float4*)&Bf[kk*256 + tx*4];
            acc[0][0]+=a.x*b.x; acc[0][1]+=a.x*b.y; acc[0][2]+=a.x*b.z; acc[0][3]+=a.x*b.w;
            acc[1][0]+=a.y*b.x; acc[1][1]+=a.y*b.y; acc[1][2]+=a.y*b.z; acc[1][3]+=a.y*b.w;
            acc[2][0]+=a.z*b.x; acc[2][1]+=a.z*b.y; acc[2][2]+=a.z*b.z; acc[2][3]+=a.z*b.w;
            acc[3][0]+=a.w*b.x; acc[3][1]+=a.w*b.y; acc[3][2]+=a.w*b.z; acc[3][3]+=a.w*b.w;
        }
        __syncthreads();
    }
    {
        int n = half*64 + tx;
        const float* bP = g_bdecP + half*256;
        float b0 = bP[tx*4+0], b1 = bP[tx*4+1], b2 = bP[tx*4+2], b3 = bP[tx*4+3];
        #pragma unroll
        for (int q = 0; q < 4; q++){
            int row = row0 + ty*4 + q;
            float ig = sigf (acc[q][0] + b0);
            float fg = sigf (acc[q][1] + b1);
            float gg = tanhf(acc[q][2] + b2);
            float og = sigf (acc[q][3] + b3);
            float cn = fg*g_cde[row*HH + n] + ig*gg;
            g_cde[row*HH + n] = cn;
            g_hde[row*HH + n] = og*tanhf(cn);
        }
    }
}

// ---------------- decoder: hproj = h_de @ dd_w[i][128:256] + dd_b[i] ----------------
__global__ void hproj_kernel(const float* __restrict__ ddw, const float* __restrict__ ddb, int step){
    __shared__ float As[16][65];
    __shared__ float Bs[16][128];
    const float* W = ddw + step*256*128 + 128*128;
    int tid = threadIdx.x, tx = tid & 15, ty = tid >> 4;
    int row0 = blockIdx.x*64;
    float acc[4][8] = {};
    for (int k0 = 0; k0 < 128; k0 += 16){
        for (int i = tid; i < 64*16; i += 256){
            int m = i >> 4, k = i & 15, row = row0 + m;
            As[k][m] = g_hde[row*HH + k0 + k];
        }
        for (int i = tid; i < 16*128; i += 256){
            int kk = i >> 7, n = i & 127;
            Bs[kk][n] = W[(k0+kk)*128 + n];
        }
        __syncthreads();
        #pragma unroll
        for (int kk = 0; kk < 16; kk++){
            float a[4];
            #pragma unroll
            for (int q = 0; q < 4; q++) a[q] = As[kk][ty*4+q];
            float4 b0 = *(const float4*)&Bs[kk][tx*8];
            float4 b1 = *(const float4*)&Bs[kk][tx*8+4];
            #pragma unroll
            for (int q = 0; q < 4; q++){
                acc[q][0]+=a[q]*b0.x; acc[q][1]+=a[q]*b0.y; acc[q][2]+=a[q]*b0.z; acc[q][3]+=a[q]*b0.w;
                acc[q][4]+=a[q]*b1.x; acc[q][5]+=a[q]*b1.y; acc[q][6]+=a[q]*b1.z; acc[q][7]+=a[q]*b1.w;
            }
        }
        __syncthreads();
    }
    #pragma unroll
    for (int q = 0; q < 4; q++){
        int row = row0 + ty*4 + q;
        #pragma unroll
        for (int j = 0; j < 8; j++){
            int n = tx*8 + j;
            g_hproj[row*HH + n] = acc[q][j] + ddb[step*128 + n];
        }
    }
}

// ---------------- decoder temporal attention scores, 128x128 tile ----------------
__global__ void dattn_kernel(const float* __restrict__ ddw, const float* __restrict__ dlw,
                             const float* __restrict__ dlb, int step){
    __shared__ float sA[16*136];
    __shared__ float sB[16][128];
    __shared__ float sdl[128];
    __shared__ float red[128][17];
    int tid = threadIdx.x, tx = tid & 15, ty = tid >> 4;
    int row0 = blockIdx.x * 128;
    if (tid < 128) sdl[tid] = dlw[step*128 + tid];
    const float* W = ddw + step*256*128;
    float acc[8][8] = {};
    for (int k0 = 0; k0 < 128; k0 += 16){
        for (int i = tid; i < 128*16; i += 256){
            int m = i >> 4, k = i & 15;
            sA[k*136 + m] = g_enc[(row0+m)*HH + k0 + k];
        }
        for (int i = tid; i < 16*128; i += 256){
            int k = i >> 7, n = i & 127;
            sB[k][n] = W[(k0+k)*128 + n];
        }
        __syncthreads();
        #pragma unroll
        for (int kk = 0; kk < 16; kk++){
            float4 a0 = *(const float4*)&sA[kk*136 + ty*8];
            float4 a1 = *(const float4*)&sA[kk*136 + ty*8 + 4];
            float a[8] = {a0.x,a0.y,a0.z,a0.w,a1.x,a1.y,a1.z,a1.w};
            float4 b0 = *(const float4*)&sB[kk][tx*8];
            float4 b1 = *(const float4*)&sB[kk][tx*8+4];
            #pragma unroll
            for (int q = 0; q < 8; q++){
                acc[q][0]+=a[q]*b0.x; acc[q][1]+=a[q]*b0.y; acc[q][2]+=a[q]*b0.z; acc[q][3]+=a[q]*b0.w;
                acc[q][4]+=a[q]*b1.x; acc[q][5]+=a[q]*b1.y; acc[q][6]+=a[q]*b1.z; acc[q][7]+=a[q]*b1.w;
            }
        }
        __syncthreads();
    }
    #pragma unroll
    for (int q = 0; q < 8; q++){
        int row = row0 + ty*8 + q;
        int bb = row / LL;
        float p = 0.f;
        #pragma unroll
        for (int j = 0; j < 8; j++){
            int n = tx*8 + j;
            p += tanhf(acc[q][j] + g_hproj[bb*HH + n]) * sdl[n];
        }
        red[ty*8+q][tx] = p;
    }
    __syncthreads();
    if (tid < 128){
        float s = 0.f;
        #pragma unroll
        for (int xk = 0; xk < 16; xk++) s += red[tid][xk];
        g_e2[row0 + tid] = s + dlb[step];
    }
}

// ---------------- softmax over L + context ----------------
__global__ void softctx_kernel(){
    __shared__ float sal[LL];
    __shared__ float sinv;
    int b = blockIdx.x, tid = threadIdx.x;  // 128 threads
    if (tid < LL) sal[tid] = g_e2[b*LL + tid];
    __syncthreads();
    if (tid == 0){
        float mx = -1e30f;
        for (int l = 0; l < LL; l++) mx = fmaxf(mx, sal[l]);
        float s = 0.f;
        for (int l = 0; l < LL; l++){ float e = __expf(sal[l]-mx); sal[l]=e; s+=e; }
        sinv = 1.f/s;
    }
    __syncthreads();
    float a = 0.f;
    #pragma unroll 5
    for (int l = 0; l < LL; l++) a += sal[l]*g_enc[(b*LL + l)*HH + tid];
    g_ctx[b*HH + tid] = a*sinv;
}

// ---------------- output head ----------------
__global__ void head_kernel(const float* __restrict__ fcw, const float* __restrict__ fcb,
                            const float* __restrict__ ow,  const float* __restrict__ ob,
                            float* __restrict__ out, int step){
    __shared__ float sh[128];
    __shared__ float sp[2];
    int b = blockIdx.x, tid = threadIdx.x;  // 64 threads
    sh[tid]      = g_hde[b*HH + tid];
    sh[tid + 64] = g_hde[b*HH + 64 + tid];
    __syncthreads();
    float s = fcb[step*64 + tid];
    const float* W = fcw + step*HH*64;
    #pragma unroll 8
    for (int k = 0; k < 128; k++) s += sh[k]*W[k*64 + tid];
    float y = tanhf(s)*ow[step*64 + tid];
    #pragma unroll
    for (int off = 16; off; off >>= 1) y += __shfl_down_sync(0xffffffffu, y, off);
    if ((tid & 31) == 0) sp[tid >> 5] = y;
    __syncthreads();
    if (tid == 0){
        float r = sp[0] + sp[1] + ob[step];
        out[b*NOUTS + step] = 1.f/(1.f + __expf(-r));
    }
}

// ---------------- launcher ----------------
extern "C" void kernel_launch(void* const* d_in, const int* in_sizes, int n_in,
                              void* d_out, int out_size){
    const float* x     = (const float*)d_in[0];
    const float* eWih  = (const float*)d_in[1];
    const float* eWhh  = (const float*)d_in[2];
    const float* ebih  = (const float*)d_in[3];
    const float* ebhh  = (const float*)d_in[4];
    const float* attw  = (const float*)d_in[5];
    const float* attb  = (const float*)d_in[6];
    const float* dWih  = (const float*)d_in[7];
    const float* dWhh  = (const float*)d_in[8];
    const float* dbih  = (const float*)d_in[9];
    const float* dbhh  = (const float*)d_in[10];
    const float* ddw   = (const float*)d_in[11];
    const float* ddb   = (const float*)d_in[12];
    const float* dlw   = (const float*)d_in[13];
    const float* dlb   = (const float*)d_in[14];
    const float* fcw   = (const float*)d_in[15];
    const float* fcb   = (const float*)d_in[16];
    const float* ow    = (const float*)d_in[17];
    const float* ob    = (const float*)d_in[18];
    float* out = (float*)d_out;

    const int ENC_SMEM = 23552 * 4;          // 94,208 B -> 2 blocks/SM
    const int DEC_SMEM = (7680 + 8192) * 4;  // 63,488 B
    cudaFuncSetAttribute(enc_persist_kernel, cudaFuncAttributeMaxDynamicSharedMemorySize, ENC_SMEM);
    cudaFuncSetAttribute(dec_step_kernel, cudaFuncAttributeMaxDynamicSharedMemorySize, DEC_SMEM);

    zero_kernel<<<(BB*HH + 255)/256, 256>>>();
    prep_kernel<<<(2*KDEC*256 + 255)/256, 256>>>(eWih, eWhh, ebih, ebhh, dWih, dWhh, dbih, dbhh);

    enc_persist_kernel<<<BB/BM, 256, ENC_SMEM>>>(x, attw, attb);

    for (int i = 0; i < NOUTS; i++){
        hproj_kernel<<<BB/64, 256>>>(ddw, ddb, i);
        dattn_kernel<<<(BB*LL)/128, 256>>>(ddw, dlw, dlb, i);
        softctx_kernel<<<BB, 128>>>();
        dec_step_kernel<<<dim3(2, BB/16), 256, DEC_SMEM>>>();
        head_kernel<<<BB, 64>>>(fcw, fcb, ow, ob, out, i);
    }
}